// round 1
// baseline (speedup 1.0000x reference)
#include <cuda_runtime.h>
#include <math.h>

// Problem constants
#define BSZ 4
#define TLEN 2048
#define CDIM 768
#define HN 12
#define DH 64
#define ROWSTRIDE (3*CDIM)   // 2304

// Scratch (allocation-free rule: __device__ globals)
__device__ float g_qkv[(size_t)BSZ*TLEN*3*CDIM];  // [B,T,3C]
__device__ float g_y  [(size_t)BSZ*TLEN*CDIM];    // [B,T,C] attention output (merged heads)

// ---------------------------------------------------------------------------
// SGEMM + bias: C[M,N] = A[M,K] @ B[K,N] + bias[N]
// 128x128 block tile, K-step 8, 256 threads, 8x8 per thread.
// Requires M%128==0, N%128==0, K%8==0 (true for all uses here).
// ---------------------------------------------------------------------------
__global__ __launch_bounds__(256) void sgemm_bias_kernel(
    const float* __restrict__ A, const float* __restrict__ Bm,
    const float* __restrict__ bias, float* __restrict__ Cm,
    int M, int N, int K)
{
    __shared__ float As[8][128];
    __shared__ float Bs[8][128];

    const int tid = threadIdx.x;
    const int bx = blockIdx.x;   // N tile
    const int by = blockIdx.y;   // M tile
    const int ty = tid >> 4;     // 0..15
    const int tx = tid & 15;     // 0..15

    // A tile load: 128 rows x 8 cols, one float4 per thread
    const int arow = tid >> 1;          // 0..127
    const int acol = (tid & 1) * 4;     // 0 or 4
    // B tile load: 8 rows x 128 cols, one float4 per thread
    const int brow = tid >> 5;          // 0..7
    const int bcol = (tid & 31) * 4;    // 0..124

    const float* Aptr = A + (size_t)(by*128 + arow)*K + acol;
    const float* Bptr = Bm + (size_t)brow*N + bx*128 + bcol;

    float acc[8][8];
#pragma unroll
    for (int i = 0; i < 8; i++)
#pragma unroll
        for (int j = 0; j < 8; j++) acc[i][j] = 0.0f;

    for (int kt = 0; kt < K; kt += 8) {
        float4 av = *reinterpret_cast<const float4*>(Aptr + kt);
        As[acol+0][arow] = av.x;
        As[acol+1][arow] = av.y;
        As[acol+2][arow] = av.z;
        As[acol+3][arow] = av.w;
        float4 bv = *reinterpret_cast<const float4*>(Bptr + (size_t)kt*N);
        *reinterpret_cast<float4*>(&Bs[brow][bcol]) = bv;
        __syncthreads();

#pragma unroll
        for (int k = 0; k < 8; k++) {
            float4 a0 = *reinterpret_cast<float4*>(&As[k][ty*8]);
            float4 a1 = *reinterpret_cast<float4*>(&As[k][ty*8+4]);
            float4 b0 = *reinterpret_cast<float4*>(&Bs[k][tx*8]);
            float4 b1 = *reinterpret_cast<float4*>(&Bs[k][tx*8+4]);
            float ar[8] = {a0.x,a0.y,a0.z,a0.w,a1.x,a1.y,a1.z,a1.w};
            float br[8] = {b0.x,b0.y,b0.z,b0.w,b1.x,b1.y,b1.z,b1.w};
#pragma unroll
            for (int i = 0; i < 8; i++)
#pragma unroll
                for (int j = 0; j < 8; j++)
                    acc[i][j] = fmaf(ar[i], br[j], acc[i][j]);
        }
        __syncthreads();
    }

    // Epilogue with bias
    const int col0 = bx*128 + tx*8;
    float4 bb0 = *reinterpret_cast<const float4*>(bias + col0);
    float4 bb1 = *reinterpret_cast<const float4*>(bias + col0 + 4);
    float bl[8] = {bb0.x,bb0.y,bb0.z,bb0.w,bb1.x,bb1.y,bb1.z,bb1.w};
#pragma unroll
    for (int i = 0; i < 8; i++) {
        const int row = by*128 + ty*8 + i;
        float* cp = Cm + (size_t)row*N + col0;
        float4 o0, o1;
        o0.x = acc[i][0]+bl[0]; o0.y = acc[i][1]+bl[1];
        o0.z = acc[i][2]+bl[2]; o0.w = acc[i][3]+bl[3];
        o1.x = acc[i][4]+bl[4]; o1.y = acc[i][5]+bl[5];
        o1.z = acc[i][6]+bl[6]; o1.w = acc[i][7]+bl[7];
        *reinterpret_cast<float4*>(cp)   = o0;
        *reinterpret_cast<float4*>(cp+4) = o1;
    }
}

// ---------------------------------------------------------------------------
// Flash attention (causal), one 64-query tile per block, D=64.
// grid = (T/64, B*H), 256 threads, dynamic smem.
// qkv layout: [B, T, 3C]; q at +h*64, k at +C+h*64, v at +2C+h*64.
// Output y: [B, T, C] with head h at column h*64.
// ---------------------------------------------------------------------------
#define SQ_STRIDE 64
#define SP_STRIDE 65   // padded for bank-conflict reduction

__global__ __launch_bounds__(256) void attn_kernel(
    const float* __restrict__ qkv, float* __restrict__ y)
{
    extern __shared__ float sm[];
    float* sQ  = sm;                       // 64*64
    float* sK  = sQ + 64*SQ_STRIDE;        // 64*65
    float* sV  = sK + 64*SP_STRIDE;        // 64*65
    float* sS  = sV + 64*SP_STRIDE;        // 64*65
    float* sM  = sS + 64*SP_STRIDE;        // 64
    float* sL  = sM + 64;                  // 64
    float* sAl = sL + 64;                  // 64

    const int qt  = blockIdx.x;            // query tile
    const int bh  = blockIdx.y;
    const int b   = bh / HN;
    const int h   = bh % HN;
    const int tid = threadIdx.x;
    const int ty  = tid >> 4;              // 0..15 -> 4 rows each
    const int tx  = tid & 15;              // 0..15 -> 4 cols each

    const float* base = qkv + (size_t)b*TLEN*ROWSTRIDE + h*DH;

    // Load Q tile (64x64)
#pragma unroll
    for (int i = 0; i < 4; i++) {
        int idx = tid + i*256;
        int r   = idx >> 4;
        int c4  = (idx & 15) * 4;
        float4 v = *reinterpret_cast<const float4*>(
            base + (size_t)(qt*64 + r)*ROWSTRIDE + c4);
        *reinterpret_cast<float4*>(&sQ[r*SQ_STRIDE + c4]) = v;
    }
    if (tid < 64) { sM[tid] = -INFINITY; sL[tid] = 0.0f; }

    float o[4][4];
#pragma unroll
    for (int i = 0; i < 4; i++)
#pragma unroll
        for (int j = 0; j < 4; j++) o[i][j] = 0.0f;

    __syncthreads();

    const float scale = 0.125f;  // 1/sqrt(64)
    const int rg0 = qt*64 + ty*4;

    for (int kt = 0; kt <= qt; kt++) {
        // Load K and V tiles (64x64 each)
#pragma unroll
        for (int i = 0; i < 4; i++) {
            int idx = tid + i*256;
            int r   = idx >> 4;
            int c4  = (idx & 15) * 4;
            const float* kp = base + (size_t)(kt*64 + r)*ROWSTRIDE + CDIM  + c4;
            const float* vp = base + (size_t)(kt*64 + r)*ROWSTRIDE + 2*CDIM + c4;
            float4 kv = *reinterpret_cast<const float4*>(kp);
            float4 vv = *reinterpret_cast<const float4*>(vp);
            float* kd = &sK[r*SP_STRIDE + c4];
            kd[0]=kv.x; kd[1]=kv.y; kd[2]=kv.z; kd[3]=kv.w;
            float* vd = &sV[r*SP_STRIDE + c4];
            vd[0]=vv.x; vd[1]=vv.y; vd[2]=vv.z; vd[3]=vv.w;
        }
        __syncthreads();

        // S = Q @ K^T (4x4 per thread over d=64)
        float s[4][4];
#pragma unroll
        for (int i = 0; i < 4; i++)
#pragma unroll
            for (int j = 0; j < 4; j++) s[i][j] = 0.0f;

#pragma unroll 8
        for (int d = 0; d < 64; d++) {
            float a[4], kb[4];
#pragma unroll
            for (int i = 0; i < 4; i++) a[i]  = sQ[(ty*4+i)*SQ_STRIDE + d];
#pragma unroll
            for (int j = 0; j < 4; j++) kb[j] = sK[(tx*4+j)*SP_STRIDE + d];
#pragma unroll
            for (int i = 0; i < 4; i++)
#pragma unroll
                for (int j = 0; j < 4; j++)
                    s[i][j] = fmaf(a[i], kb[j], s[i][j]);
        }

        // scale + causal mask + store to smem
        const int cg0 = kt*64 + tx*4;
#pragma unroll
        for (int i = 0; i < 4; i++)
#pragma unroll
            for (int j = 0; j < 4; j++) {
                float v = s[i][j] * scale;
                if (cg0 + j > rg0 + i) v = -1e30f;
                sS[(ty*4+i)*SP_STRIDE + tx*4 + j] = v;
            }
        __syncthreads();

        // Online softmax row update (64 threads, one row each)
        if (tid < 64) {
            const int r = tid;
            float m_old = sM[r];
            float mx = m_old;
            const float* srow = &sS[r*SP_STRIDE];
#pragma unroll 8
            for (int j = 0; j < 64; j++) mx = fmaxf(mx, srow[j]);
            float alpha = __expf(m_old - mx);
            float l = sL[r] * alpha;
            float* prow = &sS[r*SP_STRIDE];
#pragma unroll 8
            for (int j = 0; j < 64; j++) {
                float p = __expf(prow[j] - mx);
                prow[j] = p;
                l += p;
            }
            sM[r] = mx; sL[r] = l; sAl[r] = alpha;
        }
        __syncthreads();

        // O = O*alpha + P @ V
#pragma unroll
        for (int i = 0; i < 4; i++) {
            float al = sAl[ty*4+i];
#pragma unroll
            for (int j = 0; j < 4; j++) o[i][j] *= al;
        }
#pragma unroll 8
        for (int jj = 0; jj < 64; jj++) {
            float p[4], vv[4];
#pragma unroll
            for (int i = 0; i < 4; i++) p[i]  = sS[(ty*4+i)*SP_STRIDE + jj];
#pragma unroll
            for (int j = 0; j < 4; j++) vv[j] = sV[jj*SP_STRIDE + tx*4 + j];
#pragma unroll
            for (int i = 0; i < 4; i++)
#pragma unroll
                for (int j = 0; j < 4; j++)
                    o[i][j] = fmaf(p[i], vv[j], o[i][j]);
        }
        __syncthreads();   // protect sK/sV/sS for next iteration
    }

    // Normalize and write out
#pragma unroll
    for (int i = 0; i < 4; i++) {
        float inv_l = 1.0f / sL[ty*4+i];
        float* yp = y + (size_t)(b*TLEN + qt*64 + ty*4 + i)*CDIM + h*DH + tx*4;
#pragma unroll
        for (int j = 0; j < 4; j++) yp[j] = o[i][j] * inv_l;
    }
}

// ---------------------------------------------------------------------------
// Launch
// ---------------------------------------------------------------------------
extern "C" void kernel_launch(void* const* d_in, const int* in_sizes, int n_in,
                              void* d_out, int out_size)
{
    (void)in_sizes; (void)n_in; (void)out_size;
    const float* x      = (const float*)d_in[0];
    const float* W_attn = (const float*)d_in[1];
    const float* b_attn = (const float*)d_in[2];
    const float* W_proj = (const float*)d_in[3];
    const float* b_proj = (const float*)d_in[4];
    float* out = (float*)d_out;

    float* qkv_ptr = nullptr;
    float* y_ptr   = nullptr;
    cudaGetSymbolAddress((void**)&qkv_ptr, g_qkv);
    cudaGetSymbolAddress((void**)&y_ptr,   g_y);

    const int M = BSZ*TLEN;     // 8192

    // 1) QKV projection: [8192,768] @ [768,2304] + bias
    {
        dim3 grid(3*CDIM/128, M/128);   // (18, 64)
        sgemm_bias_kernel<<<grid, 256>>>(x, W_attn, b_attn, qkv_ptr,
                                         M, 3*CDIM, CDIM);
    }

    // 2) Causal flash attention
    {
        const int smem_bytes = (64*SQ_STRIDE + 3*64*SP_STRIDE + 3*64) * sizeof(float);
        cudaFuncSetAttribute(attn_kernel,
                             cudaFuncAttributeMaxDynamicSharedMemorySize,
                             smem_bytes);
        dim3 grid(TLEN/64, BSZ*HN);     // (32, 48)
        attn_kernel<<<grid, 256, smem_bytes>>>(qkv_ptr, y_ptr);
    }

    // 3) Output projection: [8192,768] @ [768,768] + bias
    {
        dim3 grid(CDIM/128, M/128);     // (6, 64)
        sgemm_bias_kernel<<<grid, 256>>>(y_ptr, W_proj, b_proj, out,
                                         M, CDIM, CDIM);
    }
}

// round 3
// speedup vs baseline: 1.3745x; 1.3745x over previous
#include <cuda_runtime.h>
#include <cuda_bf16.h>
#include <math.h>
#include <stdint.h>

// Problem constants
#define BSZ 4
#define TLEN 2048
#define CDIM 768
#define HN 12
#define DH 64
#define ROWSTRIDE (3*CDIM)   // 2304
#define MROWS (BSZ*TLEN)     // 8192

// ---------------------------------------------------------------------------
// Scratch (__device__ globals; allocation-free rule)
// ---------------------------------------------------------------------------
__device__ float g_qkv[(size_t)BSZ*TLEN*3*CDIM];           // [B,T,3C]
__device__ float g_y  [(size_t)BSZ*TLEN*CDIM];             // [B,T,C]
__device__ __nv_bfloat16 g_ah[(size_t)MROWS*CDIM];         // activation hi [M,K]
__device__ __nv_bfloat16 g_al[(size_t)MROWS*CDIM];         // activation lo [M,K]
__device__ __nv_bfloat16 g_wah[(size_t)(3*CDIM)*CDIM];     // W_attn^T hi [N,K]
__device__ __nv_bfloat16 g_wal[(size_t)(3*CDIM)*CDIM];     // W_attn^T lo
__device__ __nv_bfloat16 g_wph[(size_t)CDIM*CDIM];         // W_proj^T hi
__device__ __nv_bfloat16 g_wpl[(size_t)CDIM*CDIM];         // W_proj^T lo

// ---------------------------------------------------------------------------
// helpers
// ---------------------------------------------------------------------------
__device__ __forceinline__ uint32_t smem_u32(const void* p) {
    uint32_t a;
    asm("{ .reg .u64 t; cvta.to.shared.u64 t, %1; cvt.u32.u64 %0, t; }"
        : "=r"(a) : "l"(p));
    return a;
}

__device__ __forceinline__ void ldsm_x4(uint32_t& r0, uint32_t& r1,
                                        uint32_t& r2, uint32_t& r3,
                                        uint32_t addr) {
    asm volatile("ldmatrix.sync.aligned.m8n8.x4.shared.b16 {%0,%1,%2,%3}, [%4];"
                 : "=r"(r0), "=r"(r1), "=r"(r2), "=r"(r3) : "r"(addr));
}

__device__ __forceinline__ void mma_bf16(float& d0, float& d1, float& d2, float& d3,
                                         uint32_t a0, uint32_t a1, uint32_t a2, uint32_t a3,
                                         uint32_t b0, uint32_t b1) {
    asm volatile(
        "mma.sync.aligned.m16n8k16.row.col.f32.bf16.bf16.f32 "
        "{%0,%1,%2,%3}, {%4,%5,%6,%7}, {%8,%9}, {%0,%1,%2,%3};"
        : "+f"(d0), "+f"(d1), "+f"(d2), "+f"(d3)
        : "r"(a0), "r"(a1), "r"(a2), "r"(a3), "r"(b0), "r"(b1));
}

// ---------------------------------------------------------------------------
// fp32 -> (hi, lo) bf16 split, elementwise (n multiple of 4)
// ---------------------------------------------------------------------------
__global__ __launch_bounds__(256) void split_kernel(
    const float* __restrict__ in, __nv_bfloat16* __restrict__ hi,
    __nv_bfloat16* __restrict__ lo, int n4)
{
    int i = blockIdx.x * blockDim.x + threadIdx.x;
    if (i >= n4) return;
    float4 v = reinterpret_cast<const float4*>(in)[i];
    __nv_bfloat16 h0 = __float2bfloat16(v.x);
    __nv_bfloat16 h1 = __float2bfloat16(v.y);
    __nv_bfloat16 h2 = __float2bfloat16(v.z);
    __nv_bfloat16 h3 = __float2bfloat16(v.w);
    __nv_bfloat162 hp0; hp0.x = h0; hp0.y = h1;
    __nv_bfloat162 hp1; hp1.x = h2; hp1.y = h3;
    reinterpret_cast<__nv_bfloat162*>(hi)[i*2]   = hp0;
    reinterpret_cast<__nv_bfloat162*>(hi)[i*2+1] = hp1;
    __nv_bfloat162 lp0, lp1;
    lp0.x = __float2bfloat16(v.x - __bfloat162float(h0));
    lp0.y = __float2bfloat16(v.y - __bfloat162float(h1));
    lp1.x = __float2bfloat16(v.z - __bfloat162float(h2));
    lp1.y = __float2bfloat16(v.w - __bfloat162float(h3));
    reinterpret_cast<__nv_bfloat162*>(lo)[i*2]   = lp0;
    reinterpret_cast<__nv_bfloat162*>(lo)[i*2+1] = lp1;
}

// ---------------------------------------------------------------------------
// W[K,N] fp32 -> Wt hi/lo [N,K] bf16 (transpose + split). 32x32 tiles.
// ---------------------------------------------------------------------------
__global__ __launch_bounds__(256) void transpose_split_kernel(
    const float* __restrict__ W, __nv_bfloat16* __restrict__ th,
    __nv_bfloat16* __restrict__ tl, int K, int N)
{
    __shared__ float t[32][33];
    const int n0 = blockIdx.x * 32, k0 = blockIdx.y * 32;
    const int tx = threadIdx.x, ty0 = threadIdx.y;   // 32 x 8
#pragma unroll
    for (int i = 0; i < 4; i++) {
        int ty = ty0 + i*8;
        t[ty][tx] = W[(size_t)(k0 + ty) * N + n0 + tx];
    }
    __syncthreads();
#pragma unroll
    for (int i = 0; i < 4; i++) {
        int ty = ty0 + i*8;
        float v = t[tx][ty];                  // element W[k0+tx][n0+ty]
        __nv_bfloat16 h = __float2bfloat16(v);
        th[(size_t)(n0 + ty) * K + k0 + tx] = h;
        tl[(size_t)(n0 + ty) * K + k0 + tx] =
            __float2bfloat16(v - __bfloat162float(h));
    }
}

// ---------------------------------------------------------------------------
// HMMA split-bf16 GEMM: C[M,N] = (Ah+Al)[M,K] @ (Bh+Bl)[N,K]^T + bias
// 128x128 CTA tile, BK=32, 8 warps (4M x 2N), warp tile 32x64.
// grid (N/128, M/128), 256 threads. K % 32 == 0.
// ---------------------------------------------------------------------------
#define LDP 40                      // padded row length (bf16 elems) for 32-col tile
#define TILE_ELEMS (128*LDP)        // per tile
#define TILE_BYTES (TILE_ELEMS*2)   // 10240
#define BUF_TILES 4                 // Ah, Al, Bh, Bl
#define BUF_BYTES (BUF_TILES*TILE_BYTES)   // 40960
#define GEMM_SMEM_BYTES (2*BUF_BYTES)      // 81920

__global__ __launch_bounds__(256) void gemm_hmma_kernel(
    const __nv_bfloat16* __restrict__ Ah, const __nv_bfloat16* __restrict__ Al,
    const __nv_bfloat16* __restrict__ Bh, const __nv_bfloat16* __restrict__ Bl,
    const float* __restrict__ bias, float* __restrict__ Cm,
    int N, int K)
{
    extern __shared__ __nv_bfloat16 smem[];   // [2][4][128*LDP]
    const int tid  = threadIdx.x;
    const int wid  = tid >> 5;
    const int lane = tid & 31;
    const int bx = blockIdx.x, by = blockIdx.y;

    const int wm = wid & 3;          // warp row  (0..3) -> M offset 32*wm
    const int wn = wid >> 2;         // warp col  (0..1) -> N offset 64*wn

    // global sources: rows of A at by*128, rows of B(N-major) at bx*128
    const __nv_bfloat16* srcs[4];
    srcs[0] = Ah + (size_t)(by * 128) * K;
    srcs[1] = Al + (size_t)(by * 128) * K;
    srcs[2] = Bh + (size_t)(bx * 128) * K;
    srcs[3] = Bl + (size_t)(bx * 128) * K;

    // per-thread global load coords: 512 uint4 per tile / 256 thr = 2 each
    // idx = tid + q*256 ; row = idx>>2 ; col16 = idx&3  (each uint4 = 8 bf16)
    const int gr0 = tid >> 2, gc0 = (tid & 3) * 8;
    const int gr1 = (tid + 256) >> 2, gc1 = gc0;

    // smem store offsets (elements)
    const int so0 = gr0 * LDP + gc0;
    const int so1 = gr1 * LDP + gc1;

    float d[2][8][4];
#pragma unroll
    for (int mt = 0; mt < 2; mt++)
#pragma unroll
        for (int nt = 0; nt < 8; nt++)
#pragma unroll
            for (int e = 0; e < 4; e++) d[mt][nt][e] = 0.0f;

    const int KC = K / 32;

    // --- preload chunk 0 into buffer 0 ---
#pragma unroll
    for (int t = 0; t < 4; t++) {
        const __nv_bfloat16* base = srcs[t];
        __nv_bfloat16* dst = smem + t * TILE_ELEMS;
        *reinterpret_cast<uint4*>(dst + so0) =
            *reinterpret_cast<const uint4*>(base + (size_t)gr0 * K + gc0);
        *reinterpret_cast<uint4*>(dst + so1) =
            *reinterpret_cast<const uint4*>(base + (size_t)gr1 * K + gc1);
    }
    __syncthreads();

    // ldmatrix source addresses (depend only on lane + buffer base)
    // A: row = wm*32 + mt*16 + (lane&15), col = kk + (lane>>4)*8
    // B: row = wn*64 + nt2*16 + ((lane>>4)&1)*8 + (lane&7), col = kk + ((lane>>3)&1)*8
    const int a_r = (lane & 15);
    const int a_c = (lane >> 4) * 8;
    const int b_r = ((lane >> 4) & 1) * 8 + (lane & 7);
    const int b_c = ((lane >> 3) & 1) * 8;

    for (int c = 0; c < KC; c++) {
        const int cur = c & 1;
        const int nxt = cur ^ 1;
        __nv_bfloat16* buf = smem + cur * (BUF_BYTES/2);

        // prefetch next chunk to regs
        uint4 pf[4][2];
        if (c + 1 < KC) {
            const int k0 = (c + 1) * 32;
#pragma unroll
            for (int t = 0; t < 4; t++) {
                const __nv_bfloat16* base = srcs[t];
                pf[t][0] = *reinterpret_cast<const uint4*>(base + (size_t)gr0 * K + k0 + gc0);
                pf[t][1] = *reinterpret_cast<const uint4*>(base + (size_t)gr1 * K + k0 + gc1);
            }
        }

        // compute current chunk: 2 k-steps of 16
        uint32_t sAh = smem_u32(buf + 0 * TILE_ELEMS);
        uint32_t sAl = smem_u32(buf + 1 * TILE_ELEMS);
        uint32_t sBh = smem_u32(buf + 2 * TILE_ELEMS);
        uint32_t sBl = smem_u32(buf + 3 * TILE_ELEMS);

#pragma unroll
        for (int kk = 0; kk < 32; kk += 16) {
            uint32_t ah[2][4], al[2][4];
#pragma unroll
            for (int mt = 0; mt < 2; mt++) {
                uint32_t off = ((wm*32 + mt*16 + a_r) * LDP + kk + a_c) * 2;
                ldsm_x4(ah[mt][0], ah[mt][1], ah[mt][2], ah[mt][3], sAh + off);
                ldsm_x4(al[mt][0], al[mt][1], al[mt][2], al[mt][3], sAl + off);
            }
            uint32_t bh[4][4], bl[4][4];
#pragma unroll
            for (int nt2 = 0; nt2 < 4; nt2++) {
                uint32_t off = ((wn*64 + nt2*16 + b_r) * LDP + kk + b_c) * 2;
                ldsm_x4(bh[nt2][0], bh[nt2][1], bh[nt2][2], bh[nt2][3], sBh + off);
                ldsm_x4(bl[nt2][0], bl[nt2][1], bl[nt2][2], bl[nt2][3], sBl + off);
            }
#pragma unroll
            for (int mt = 0; mt < 2; mt++) {
#pragma unroll
                for (int nt2 = 0; nt2 < 4; nt2++) {
                    // n-tile 2*nt2 : B frag {r0,r1}; n-tile 2*nt2+1 : {r2,r3}
                    float* d0 = d[mt][2*nt2];
                    float* d1 = d[mt][2*nt2+1];
                    // pass 1: Ah*Bh
                    mma_bf16(d0[0],d0[1],d0[2],d0[3],
                             ah[mt][0],ah[mt][1],ah[mt][2],ah[mt][3],
                             bh[nt2][0],bh[nt2][1]);
                    mma_bf16(d1[0],d1[1],d1[2],d1[3],
                             ah[mt][0],ah[mt][1],ah[mt][2],ah[mt][3],
                             bh[nt2][2],bh[nt2][3]);
                    // pass 2: Ah*Bl
                    mma_bf16(d0[0],d0[1],d0[2],d0[3],
                             ah[mt][0],ah[mt][1],ah[mt][2],ah[mt][3],
                             bl[nt2][0],bl[nt2][1]);
                    mma_bf16(d1[0],d1[1],d1[2],d1[3],
                             ah[mt][0],ah[mt][1],ah[mt][2],ah[mt][3],
                             bl[nt2][2],bl[nt2][3]);
                    // pass 3: Al*Bh
                    mma_bf16(d0[0],d0[1],d0[2],d0[3],
                             al[mt][0],al[mt][1],al[mt][2],al[mt][3],
                             bh[nt2][0],bh[nt2][1]);
                    mma_bf16(d1[0],d1[1],d1[2],d1[3],
                             al[mt][0],al[mt][1],al[mt][2],al[mt][3],
                             bh[nt2][2],bh[nt2][3]);
                }
            }
        }

        // store prefetched chunk
        if (c + 1 < KC) {
            __nv_bfloat16* nb = smem + nxt * (BUF_BYTES/2);
#pragma unroll
            for (int t = 0; t < 4; t++) {
                __nv_bfloat16* dst = nb + t * TILE_ELEMS;
                *reinterpret_cast<uint4*>(dst + so0) = pf[t][0];
                *reinterpret_cast<uint4*>(dst + so1) = pf[t][1];
            }
        }
        __syncthreads();
    }

    // ------------------- epilogue: bias + store -------------------
    const int row_base = by * 128 + wm * 32;
    const int col_base = bx * 128 + wn * 64;
    const int lr = lane >> 2;           // 0..7
    const int lc = (lane & 3) * 2;      // 0,2,4,6
#pragma unroll
    for (int mt = 0; mt < 2; mt++) {
        const int r0 = row_base + mt*16 + lr;
        const int r1 = r0 + 8;
#pragma unroll
        for (int nt = 0; nt < 8; nt++) {
            const int cc = col_base + nt*8 + lc;
            float b0 = __ldg(bias + cc), b1 = __ldg(bias + cc + 1);
            float2 o0; o0.x = d[mt][nt][0] + b0; o0.y = d[mt][nt][1] + b1;
            float2 o1; o1.x = d[mt][nt][2] + b0; o1.y = d[mt][nt][3] + b1;
            *reinterpret_cast<float2*>(Cm + (size_t)r0 * N + cc) = o0;
            *reinterpret_cast<float2*>(Cm + (size_t)r1 * N + cc) = o1;
        }
    }
}

// ---------------------------------------------------------------------------
// Flash attention (causal), fp32 — unchanged (passing baseline).
// ---------------------------------------------------------------------------
#define SQ_STRIDE 64
#define SP_STRIDE 65

__global__ __launch_bounds__(256) void attn_kernel(
    const float* __restrict__ qkv, float* __restrict__ y)
{
    extern __shared__ float sm[];
    float* sQ  = sm;
    float* sK  = sQ + 64*SQ_STRIDE;
    float* sV  = sK + 64*SP_STRIDE;
    float* sS  = sV + 64*SP_STRIDE;
    float* sM  = sS + 64*SP_STRIDE;
    float* sL  = sM + 64;
    float* sAl = sL + 64;

    const int qt  = blockIdx.x;
    const int bh  = blockIdx.y;
    const int b   = bh / HN;
    const int h   = bh % HN;
    const int tid = threadIdx.x;
    const int ty  = tid >> 4;
    const int tx  = tid & 15;

    const float* base = qkv + (size_t)b*TLEN*ROWSTRIDE + h*DH;

#pragma unroll
    for (int i = 0; i < 4; i++) {
        int idx = tid + i*256;
        int r   = idx >> 4;
        int c4  = (idx & 15) * 4;
        float4 v = *reinterpret_cast<const float4*>(
            base + (size_t)(qt*64 + r)*ROWSTRIDE + c4);
        *reinterpret_cast<float4*>(&sQ[r*SQ_STRIDE + c4]) = v;
    }
    if (tid < 64) { sM[tid] = -INFINITY; sL[tid] = 0.0f; }

    float o[4][4];
#pragma unroll
    for (int i = 0; i < 4; i++)
#pragma unroll
        for (int j = 0; j < 4; j++) o[i][j] = 0.0f;

    __syncthreads();

    const float scale = 0.125f;
    const int rg0 = qt*64 + ty*4;

    for (int kt = 0; kt <= qt; kt++) {
#pragma unroll
        for (int i = 0; i < 4; i++) {
            int idx = tid + i*256;
            int r   = idx >> 4;
            int c4  = (idx & 15) * 4;
            const float* kp = base + (size_t)(kt*64 + r)*ROWSTRIDE + CDIM  + c4;
            const float* vp = base + (size_t)(kt*64 + r)*ROWSTRIDE + 2*CDIM + c4;
            float4 kv = *reinterpret_cast<const float4*>(kp);
            float4 vv = *reinterpret_cast<const float4*>(vp);
            float* kd = &sK[r*SP_STRIDE + c4];
            kd[0]=kv.x; kd[1]=kv.y; kd[2]=kv.z; kd[3]=kv.w;
            float* vd = &sV[r*SP_STRIDE + c4];
            vd[0]=vv.x; vd[1]=vv.y; vd[2]=vv.z; vd[3]=vv.w;
        }
        __syncthreads();

        float s[4][4];
#pragma unroll
        for (int i = 0; i < 4; i++)
#pragma unroll
            for (int j = 0; j < 4; j++) s[i][j] = 0.0f;

#pragma unroll 8
        for (int d = 0; d < 64; d++) {
            float a[4], kb[4];
#pragma unroll
            for (int i = 0; i < 4; i++) a[i]  = sQ[(ty*4+i)*SQ_STRIDE + d];
#pragma unroll
            for (int j = 0; j < 4; j++) kb[j] = sK[(tx*4+j)*SP_STRIDE + d];
#pragma unroll
            for (int i = 0; i < 4; i++)
#pragma unroll
                for (int j = 0; j < 4; j++)
                    s[i][j] = fmaf(a[i], kb[j], s[i][j]);
        }

        const int cg0 = kt*64 + tx*4;
#pragma unroll
        for (int i = 0; i < 4; i++)
#pragma unroll
            for (int j = 0; j < 4; j++) {
                float v = s[i][j] * scale;
                if (cg0 + j > rg0 + i) v = -1e30f;
                sS[(ty*4+i)*SP_STRIDE + tx*4 + j] = v;
            }
        __syncthreads();

        if (tid < 64) {
            const int r = tid;
            float m_old = sM[r];
            float mx = m_old;
            const float* srow = &sS[r*SP_STRIDE];
#pragma unroll 8
            for (int j = 0; j < 64; j++) mx = fmaxf(mx, srow[j]);
            float alpha = __expf(m_old - mx);
            float l = sL[r] * alpha;
            float* prow = &sS[r*SP_STRIDE];
#pragma unroll 8
            for (int j = 0; j < 64; j++) {
                float p = __expf(prow[j] - mx);
                prow[j] = p;
                l += p;
            }
            sM[r] = mx; sL[r] = l; sAl[r] = alpha;
        }
        __syncthreads();

#pragma unroll
        for (int i = 0; i < 4; i++) {
            float al = sAl[ty*4+i];
#pragma unroll
            for (int j = 0; j < 4; j++) o[i][j] *= al;
        }
#pragma unroll 8
        for (int jj = 0; jj < 64; jj++) {
            float p[4], vv[4];
#pragma unroll
            for (int i = 0; i < 4; i++) p[i]  = sS[(ty*4+i)*SP_STRIDE + jj];
#pragma unroll
            for (int j = 0; j < 4; j++) vv[j] = sV[jj*SP_STRIDE + tx*4 + j];
#pragma unroll
            for (int i = 0; i < 4; i++)
#pragma unroll
                for (int j = 0; j < 4; j++)
                    o[i][j] = fmaf(p[i], vv[j], o[i][j]);
        }
        __syncthreads();
    }

#pragma unroll
    for (int i = 0; i < 4; i++) {
        float inv_l = 1.0f / sL[ty*4+i];
        float* yp = y + (size_t)(b*TLEN + qt*64 + ty*4 + i)*CDIM + h*DH + tx*4;
#pragma unroll
        for (int j = 0; j < 4; j++) yp[j] = o[i][j] * inv_l;
    }
}

// ---------------------------------------------------------------------------
// Launch
// ---------------------------------------------------------------------------
extern "C" void kernel_launch(void* const* d_in, const int* in_sizes, int n_in,
                              void* d_out, int out_size)
{
    (void)in_sizes; (void)n_in; (void)out_size;
    const float* x      = (const float*)d_in[0];
    const float* W_attn = (const float*)d_in[1];
    const float* b_attn = (const float*)d_in[2];
    const float* W_proj = (const float*)d_in[3];
    const float* b_proj = (const float*)d_in[4];
    float* out = (float*)d_out;

    float *qkv_ptr, *y_ptr;
    __nv_bfloat16 *ah, *al, *wah, *wal, *wph, *wpl;
    cudaGetSymbolAddress((void**)&qkv_ptr, g_qkv);
    cudaGetSymbolAddress((void**)&y_ptr,   g_y);
    cudaGetSymbolAddress((void**)&ah,  g_ah);
    cudaGetSymbolAddress((void**)&al,  g_al);
    cudaGetSymbolAddress((void**)&wah, g_wah);
    cudaGetSymbolAddress((void**)&wal, g_wal);
    cudaGetSymbolAddress((void**)&wph, g_wph);
    cudaGetSymbolAddress((void**)&wpl, g_wpl);

    static bool attr_set = false;
    if (!attr_set) {
        cudaFuncSetAttribute(gemm_hmma_kernel,
                             cudaFuncAttributeMaxDynamicSharedMemorySize,
                             GEMM_SMEM_BYTES);
        const int attn_smem = (64*SQ_STRIDE + 3*64*SP_STRIDE + 3*64) * sizeof(float);
        cudaFuncSetAttribute(attn_kernel,
                             cudaFuncAttributeMaxDynamicSharedMemorySize,
                             attn_smem);
        attr_set = true;
    }

    const int M = MROWS;   // 8192

    // Prep: split x; transpose+split weights
    {
        int n4 = M * CDIM / 4;
        split_kernel<<<(n4 + 255)/256, 256>>>(x, ah, al, n4);
        dim3 tb(32, 8);
        transpose_split_kernel<<<dim3(3*CDIM/32, CDIM/32), tb>>>(W_attn, wah, wal, CDIM, 3*CDIM);
        transpose_split_kernel<<<dim3(CDIM/32, CDIM/32), tb>>>(W_proj, wph, wpl, CDIM, CDIM);
    }

    // 1) QKV: [8192,768] x [768,2304]^T(N,K) + bias -> g_qkv
    gemm_hmma_kernel<<<dim3(3*CDIM/128, M/128), 256, GEMM_SMEM_BYTES>>>(
        ah, al, wah, wal, b_attn, qkv_ptr, 3*CDIM, CDIM);

    // 2) Causal flash attention -> g_y
    {
        const int attn_smem = (64*SQ_STRIDE + 3*64*SP_STRIDE + 3*64) * sizeof(float);
        attn_kernel<<<dim3(TLEN/64, BSZ*HN), 256, attn_smem>>>(qkv_ptr, y_ptr);
    }

    // 3) split y, then proj: [8192,768] x [768,768]^T + bias -> out
    {
        int n4 = M * CDIM / 4;
        split_kernel<<<(n4 + 255)/256, 256>>>(y_ptr, ah, al, n4);
    }
    gemm_hmma_kernel<<<dim3(CDIM/128, M/128), 256, GEMM_SMEM_BYTES>>>(
        ah, al, wph, wpl, b_proj, out, CDIM, CDIM);
}

// round 4
// speedup vs baseline: 3.0205x; 2.1976x over previous
#include <cuda_runtime.h>
#include <cuda_bf16.h>
#include <math.h>
#include <stdint.h>

// Problem constants
#define BSZ 4
#define TLEN 2048
#define CDIM 768
#define HN 12
#define DH 64
#define ROWSTRIDE (3*CDIM)   // 2304
#define MROWS (BSZ*TLEN)     // 8192

// ---------------------------------------------------------------------------
// Scratch
// ---------------------------------------------------------------------------
__device__ float g_qkv[(size_t)BSZ*TLEN*3*CDIM];           // [B,T,3C]
__device__ float g_y  [(size_t)BSZ*TLEN*CDIM];             // [B,T,C]
__device__ __nv_bfloat16 g_ah[(size_t)MROWS*CDIM];
__device__ __nv_bfloat16 g_al[(size_t)MROWS*CDIM];
__device__ __nv_bfloat16 g_wah[(size_t)(3*CDIM)*CDIM];
__device__ __nv_bfloat16 g_wal[(size_t)(3*CDIM)*CDIM];
__device__ __nv_bfloat16 g_wph[(size_t)CDIM*CDIM];
__device__ __nv_bfloat16 g_wpl[(size_t)CDIM*CDIM];
// attention operands: [B*H, T, 64] for Q/K ; [B*H, 64, T] for V (transposed)
#define AHT ((size_t)BSZ*HN*TLEN*DH)
__device__ __nv_bfloat16 g_qh2[AHT];
__device__ __nv_bfloat16 g_ql2[AHT];
__device__ __nv_bfloat16 g_kh2[AHT];
__device__ __nv_bfloat16 g_kl2[AHT];
__device__ __nv_bfloat16 g_vth[AHT];
__device__ __nv_bfloat16 g_vtl[AHT];

// ---------------------------------------------------------------------------
// helpers
// ---------------------------------------------------------------------------
__device__ __forceinline__ uint32_t smem_u32(const void* p) {
    uint32_t a;
    asm("{ .reg .u64 t; cvta.to.shared.u64 t, %1; cvt.u32.u64 %0, t; }"
        : "=r"(a) : "l"(p));
    return a;
}
__device__ __forceinline__ void ldsm_x4(uint32_t& r0, uint32_t& r1,
                                        uint32_t& r2, uint32_t& r3,
                                        uint32_t addr) {
    asm volatile("ldmatrix.sync.aligned.m8n8.x4.shared.b16 {%0,%1,%2,%3}, [%4];"
                 : "=r"(r0), "=r"(r1), "=r"(r2), "=r"(r3) : "r"(addr));
}
__device__ __forceinline__ void mma_bf16(float& d0, float& d1, float& d2, float& d3,
                                         uint32_t a0, uint32_t a1, uint32_t a2, uint32_t a3,
                                         uint32_t b0, uint32_t b1) {
    asm volatile(
        "mma.sync.aligned.m16n8k16.row.col.f32.bf16.bf16.f32 "
        "{%0,%1,%2,%3}, {%4,%5,%6,%7}, {%8,%9}, {%0,%1,%2,%3};"
        : "+f"(d0), "+f"(d1), "+f"(d2), "+f"(d3)
        : "r"(a0), "r"(a1), "r"(a2), "r"(a3), "r"(b0), "r"(b1));
}
__device__ __forceinline__ float ex2f(float x) {
    float r; asm("ex2.approx.ftz.f32 %0, %1;" : "=f"(r) : "f"(x)); return r;
}
__device__ __forceinline__ void split2(float x, float y, uint32_t& hi, uint32_t& lo) {
    __nv_bfloat162 h = __floats2bfloat162_rn(x, y);
    __nv_bfloat162 l = __floats2bfloat162_rn(x - __low2float(h), y - __high2float(h));
    hi = *reinterpret_cast<uint32_t*>(&h);
    lo = *reinterpret_cast<uint32_t*>(&l);
}

// ---------------------------------------------------------------------------
// fp32 -> (hi, lo) bf16 split, elementwise
// ---------------------------------------------------------------------------
__global__ __launch_bounds__(256) void split_kernel(
    const float* __restrict__ in, __nv_bfloat16* __restrict__ hi,
    __nv_bfloat16* __restrict__ lo, int n4)
{
    int i = blockIdx.x * blockDim.x + threadIdx.x;
    if (i >= n4) return;
    float4 v = reinterpret_cast<const float4*>(in)[i];
    __nv_bfloat162 h01 = __floats2bfloat162_rn(v.x, v.y);
    __nv_bfloat162 h23 = __floats2bfloat162_rn(v.z, v.w);
    reinterpret_cast<__nv_bfloat162*>(hi)[i*2]   = h01;
    reinterpret_cast<__nv_bfloat162*>(hi)[i*2+1] = h23;
    __nv_bfloat162 l01 = __floats2bfloat162_rn(v.x - __low2float(h01), v.y - __high2float(h01));
    __nv_bfloat162 l23 = __floats2bfloat162_rn(v.z - __low2float(h23), v.w - __high2float(h23));
    reinterpret_cast<__nv_bfloat162*>(lo)[i*2]   = l01;
    reinterpret_cast<__nv_bfloat162*>(lo)[i*2+1] = l23;
}

// ---------------------------------------------------------------------------
// W[K,N] fp32 -> Wt hi/lo [N,K] bf16 (transpose + split)
// ---------------------------------------------------------------------------
__global__ __launch_bounds__(256) void transpose_split_kernel(
    const float* __restrict__ W, __nv_bfloat16* __restrict__ th,
    __nv_bfloat16* __restrict__ tl, int K, int N)
{
    __shared__ float t[32][33];
    const int n0 = blockIdx.x * 32, k0 = blockIdx.y * 32;
    const int tx = threadIdx.x, ty0 = threadIdx.y;
#pragma unroll
    for (int i = 0; i < 4; i++) {
        int ty = ty0 + i*8;
        t[ty][tx] = W[(size_t)(k0 + ty) * N + n0 + tx];
    }
    __syncthreads();
#pragma unroll
    for (int i = 0; i < 4; i++) {
        int ty = ty0 + i*8;
        float v = t[tx][ty];
        __nv_bfloat16 h = __float2bfloat16(v);
        th[(size_t)(n0 + ty) * K + k0 + tx] = h;
        tl[(size_t)(n0 + ty) * K + k0 + tx] =
            __float2bfloat16(v - __bfloat162float(h));
    }
}

// ---------------------------------------------------------------------------
// qkv [B,T,3C] -> Q hi/lo (scaled by 0.125*log2e), K hi/lo as [B*H, T, 64]
// ---------------------------------------------------------------------------
__global__ __launch_bounds__(256) void split_qk_kernel(
    const float* __restrict__ qkv,
    __nv_bfloat16* __restrict__ Qh, __nv_bfloat16* __restrict__ Ql,
    __nv_bfloat16* __restrict__ Kh, __nv_bfloat16* __restrict__ Kl)
{
    int i = blockIdx.x * blockDim.x + threadIdx.x;
    if (i >= BSZ*TLEN*2*HN*16) return;
    int j = i;
    int d4 = j & 15; j >>= 4;
    int h  = j % HN; j /= HN;
    int s  = j & 1;  j >>= 1;
    int t  = j & (TLEN-1); j >>= 11;
    int b  = j;
    const float4 v = *reinterpret_cast<const float4*>(
        qkv + ((size_t)(b*TLEN + t))*ROWSTRIDE + s*CDIM + h*64 + d4*4);
    const float sc = s ? 1.0f : 0.18033688011112042f;  // 0.125*log2(e)
    float x0 = v.x*sc, x1 = v.y*sc, x2 = v.z*sc, x3 = v.w*sc;
    __nv_bfloat162 h01 = __floats2bfloat162_rn(x0, x1);
    __nv_bfloat162 h23 = __floats2bfloat162_rn(x2, x3);
    __nv_bfloat162 l01 = __floats2bfloat162_rn(x0 - __low2float(h01), x1 - __high2float(h01));
    __nv_bfloat162 l23 = __floats2bfloat162_rn(x2 - __low2float(h23), x3 - __high2float(h23));
    size_t dst = (((size_t)(b*HN + h))*TLEN + t)*64 + d4*4;
    __nv_bfloat16* H = s ? Kh : Qh;
    __nv_bfloat16* L = s ? Kl : Ql;
    *reinterpret_cast<__nv_bfloat162*>(H + dst)     = h01;
    *reinterpret_cast<__nv_bfloat162*>(H + dst + 2) = h23;
    *reinterpret_cast<__nv_bfloat162*>(L + dst)     = l01;
    *reinterpret_cast<__nv_bfloat162*>(L + dst + 2) = l23;
}

// ---------------------------------------------------------------------------
// V from qkv -> transposed [B*H, 64, T] hi/lo bf16
// ---------------------------------------------------------------------------
__global__ __launch_bounds__(256) void transpose_split_v_kernel(
    const float* __restrict__ qkv,
    __nv_bfloat16* __restrict__ Vh, __nv_bfloat16* __restrict__ Vl)
{
    __shared__ float t[32][33];
    const int bh = blockIdx.x;         // B*H
    const int t0 = blockIdx.y * 32;
    const int d0 = blockIdx.z * 32;
    const int b = bh / HN, h = bh % HN;
    const int tx = threadIdx.x, ty0 = threadIdx.y;
#pragma unroll
    for (int i = 0; i < 4; i++) {
        int ty = ty0 + i*8;
        t[ty][tx] = qkv[((size_t)(b*TLEN + t0 + ty))*ROWSTRIDE + 2*CDIM + h*64 + d0 + tx];
    }
    __syncthreads();
#pragma unroll
    for (int i = 0; i < 4; i++) {
        int dy = ty0 + i*8;
        float v = t[tx][dy];
        __nv_bfloat16 hi = __float2bfloat16(v);
        size_t dst = ((size_t)bh*64 + d0 + dy)*TLEN + t0 + tx;
        Vh[dst] = hi;
        Vl[dst] = __float2bfloat16(v - __bfloat162float(hi));
    }
}

// ---------------------------------------------------------------------------
// HMMA split-bf16 GEMM (unchanged from round 3, passing)
// ---------------------------------------------------------------------------
#define LDP 40
#define TILE_ELEMS (128*LDP)
#define TILE_BYTES (TILE_ELEMS*2)
#define BUF_TILES 4
#define BUF_BYTES (BUF_TILES*TILE_BYTES)
#define GEMM_SMEM_BYTES (2*BUF_BYTES)

__global__ __launch_bounds__(256) void gemm_hmma_kernel(
    const __nv_bfloat16* __restrict__ Ah, const __nv_bfloat16* __restrict__ Al,
    const __nv_bfloat16* __restrict__ Bh, const __nv_bfloat16* __restrict__ Bl,
    const float* __restrict__ bias, float* __restrict__ Cm,
    int N, int K)
{
    extern __shared__ __nv_bfloat16 smem[];
    const int tid  = threadIdx.x;
    const int wid  = tid >> 5;
    const int lane = tid & 31;
    const int bx = blockIdx.x, by = blockIdx.y;
    const int wm = wid & 3;
    const int wn = wid >> 2;

    const __nv_bfloat16* srcs[4];
    srcs[0] = Ah + (size_t)(by * 128) * K;
    srcs[1] = Al + (size_t)(by * 128) * K;
    srcs[2] = Bh + (size_t)(bx * 128) * K;
    srcs[3] = Bl + (size_t)(bx * 128) * K;

    const int gr0 = tid >> 2, gc0 = (tid & 3) * 8;
    const int gr1 = (tid + 256) >> 2, gc1 = gc0;
    const int so0 = gr0 * LDP + gc0;
    const int so1 = gr1 * LDP + gc1;

    float d[2][8][4];
#pragma unroll
    for (int mt = 0; mt < 2; mt++)
#pragma unroll
        for (int nt = 0; nt < 8; nt++)
#pragma unroll
            for (int e = 0; e < 4; e++) d[mt][nt][e] = 0.0f;

    const int KC = K / 32;

#pragma unroll
    for (int t = 0; t < 4; t++) {
        const __nv_bfloat16* base = srcs[t];
        __nv_bfloat16* dst = smem + t * TILE_ELEMS;
        *reinterpret_cast<uint4*>(dst + so0) =
            *reinterpret_cast<const uint4*>(base + (size_t)gr0 * K + gc0);
        *reinterpret_cast<uint4*>(dst + so1) =
            *reinterpret_cast<const uint4*>(base + (size_t)gr1 * K + gc1);
    }
    __syncthreads();

    const int a_r = (lane & 15);
    const int a_c = (lane >> 4) * 8;
    const int b_r = ((lane >> 4) & 1) * 8 + (lane & 7);
    const int b_c = ((lane >> 3) & 1) * 8;

    for (int c = 0; c < KC; c++) {
        const int cur = c & 1;
        const int nxt = cur ^ 1;
        __nv_bfloat16* buf = smem + cur * (BUF_BYTES/2);

        uint4 pf[4][2];
        if (c + 1 < KC) {
            const int k0 = (c + 1) * 32;
#pragma unroll
            for (int t = 0; t < 4; t++) {
                const __nv_bfloat16* base = srcs[t];
                pf[t][0] = *reinterpret_cast<const uint4*>(base + (size_t)gr0 * K + k0 + gc0);
                pf[t][1] = *reinterpret_cast<const uint4*>(base + (size_t)gr1 * K + k0 + gc1);
            }
        }

        uint32_t sAh = smem_u32(buf + 0 * TILE_ELEMS);
        uint32_t sAl = smem_u32(buf + 1 * TILE_ELEMS);
        uint32_t sBh = smem_u32(buf + 2 * TILE_ELEMS);
        uint32_t sBl = smem_u32(buf + 3 * TILE_ELEMS);

#pragma unroll
        for (int kk = 0; kk < 32; kk += 16) {
            uint32_t ah[2][4], al[2][4];
#pragma unroll
            for (int mt = 0; mt < 2; mt++) {
                uint32_t off = ((wm*32 + mt*16 + a_r) * LDP + kk + a_c) * 2;
                ldsm_x4(ah[mt][0], ah[mt][1], ah[mt][2], ah[mt][3], sAh + off);
                ldsm_x4(al[mt][0], al[mt][1], al[mt][2], al[mt][3], sAl + off);
            }
            uint32_t bh[4][4], bl[4][4];
#pragma unroll
            for (int nt2 = 0; nt2 < 4; nt2++) {
                uint32_t off = ((wn*64 + nt2*16 + b_r) * LDP + kk + b_c) * 2;
                ldsm_x4(bh[nt2][0], bh[nt2][1], bh[nt2][2], bh[nt2][3], sBh + off);
                ldsm_x4(bl[nt2][0], bl[nt2][1], bl[nt2][2], bl[nt2][3], sBl + off);
            }
#pragma unroll
            for (int mt = 0; mt < 2; mt++) {
#pragma unroll
                for (int nt2 = 0; nt2 < 4; nt2++) {
                    float* d0 = d[mt][2*nt2];
                    float* d1 = d[mt][2*nt2+1];
                    mma_bf16(d0[0],d0[1],d0[2],d0[3],
                             ah[mt][0],ah[mt][1],ah[mt][2],ah[mt][3],
                             bh[nt2][0],bh[nt2][1]);
                    mma_bf16(d1[0],d1[1],d1[2],d1[3],
                             ah[mt][0],ah[mt][1],ah[mt][2],ah[mt][3],
                             bh[nt2][2],bh[nt2][3]);
                    mma_bf16(d0[0],d0[1],d0[2],d0[3],
                             ah[mt][0],ah[mt][1],ah[mt][2],ah[mt][3],
                             bl[nt2][0],bl[nt2][1]);
                    mma_bf16(d1[0],d1[1],d1[2],d1[3],
                             ah[mt][0],ah[mt][1],ah[mt][2],ah[mt][3],
                             bl[nt2][2],bl[nt2][3]);
                    mma_bf16(d0[0],d0[1],d0[2],d0[3],
                             al[mt][0],al[mt][1],al[mt][2],al[mt][3],
                             bh[nt2][0],bh[nt2][1]);
                    mma_bf16(d1[0],d1[1],d1[2],d1[3],
                             al[mt][0],al[mt][1],al[mt][2],al[mt][3],
                             bh[nt2][2],bh[nt2][3]);
                }
            }
        }

        if (c + 1 < KC) {
            __nv_bfloat16* nb = smem + nxt * (BUF_BYTES/2);
#pragma unroll
            for (int t = 0; t < 4; t++) {
                __nv_bfloat16* dst = nb + t * TILE_ELEMS;
                *reinterpret_cast<uint4*>(dst + so0) = pf[t][0];
                *reinterpret_cast<uint4*>(dst + so1) = pf[t][1];
            }
        }
        __syncthreads();
    }

    const int row_base = by * 128 + wm * 32;
    const int col_base = bx * 128 + wn * 64;
    const int lr = lane >> 2;
    const int lc = (lane & 3) * 2;
#pragma unroll
    for (int mt = 0; mt < 2; mt++) {
        const int r0 = row_base + mt*16 + lr;
        const int r1 = r0 + 8;
#pragma unroll
        for (int nt = 0; nt < 8; nt++) {
            const int cc = col_base + nt*8 + lc;
            float b0 = __ldg(bias + cc), b1 = __ldg(bias + cc + 1);
            float2 o0; o0.x = d[mt][nt][0] + b0; o0.y = d[mt][nt][1] + b1;
            float2 o1; o1.x = d[mt][nt][2] + b0; o1.y = d[mt][nt][3] + b1;
            *reinterpret_cast<float2*>(Cm + (size_t)r0 * N + cc) = o0;
            *reinterpret_cast<float2*>(Cm + (size_t)r1 * N + cc) = o1;
        }
    }
}

// ---------------------------------------------------------------------------
// HMMA flash attention (causal). BM=128 q/block, 4 warps, key tiles of 64.
// Q pre-scaled by 0.125*log2e. QK and PV both split-bf16 (3 passes).
// ---------------------------------------------------------------------------
#define ALD 72
#define ATTN_SMEM_BYTES ((2*128*ALD + 4*64*ALD) * 2)   // 73728

__global__ __launch_bounds__(128) void attn_mma_kernel(
    const __nv_bfloat16* __restrict__ Qh, const __nv_bfloat16* __restrict__ Ql,
    const __nv_bfloat16* __restrict__ Kh, const __nv_bfloat16* __restrict__ Kl,
    const __nv_bfloat16* __restrict__ Vh, const __nv_bfloat16* __restrict__ Vl,
    float* __restrict__ y)
{
    extern __shared__ __nv_bfloat16 sab[];
    __nv_bfloat16* sQh = sab;                  // 128*ALD
    __nv_bfloat16* sQl = sQh + 128*ALD;
    __nv_bfloat16* sKh = sQl + 128*ALD;        // 64*ALD each below
    __nv_bfloat16* sKl = sKh + 64*ALD;
    __nv_bfloat16* sVh = sKl + 64*ALD;
    __nv_bfloat16* sVl = sVh + 64*ALD;

    const int tid = threadIdx.x, lane = tid & 31, wm = tid >> 5;
    const int qt = blockIdx.x, bh = blockIdx.y;
    const int b = bh / HN, h = bh % HN;

    const size_t qoff = ((size_t)bh * TLEN + (size_t)qt*128) * 64;
#pragma unroll
    for (int i = 0; i < 8; i++) {
        int idx = tid + i*128;
        int r = idx >> 3, c = (idx & 7) * 8;
        *reinterpret_cast<uint4*>(sQh + r*ALD + c) =
            *reinterpret_cast<const uint4*>(Qh + qoff + (size_t)r*64 + c);
        *reinterpret_cast<uint4*>(sQl + r*ALD + c) =
            *reinterpret_cast<const uint4*>(Ql + qoff + (size_t)r*64 + c);
    }

    float o[2][8][4];
#pragma unroll
    for (int mt = 0; mt < 2; mt++)
#pragma unroll
        for (int nt = 0; nt < 8; nt++)
#pragma unroll
            for (int e = 0; e < 4; e++) o[mt][nt][e] = 0.0f;

    const float NEG_INF = __int_as_float(0xff800000);
    float mrow[4] = {NEG_INF, NEG_INF, NEG_INF, NEG_INF};
    float lrow[4] = {0.0f, 0.0f, 0.0f, 0.0f};

    const int q0 = qt*128 + wm*32;
    const int a_r = lane & 15, a_c = (lane >> 4) * 8;
    const int b_r = ((lane >> 4) & 1) * 8 + (lane & 7);
    const int b_c = ((lane >> 3) & 1) * 8;
    const int lr = lane >> 2, lc2 = (lane & 3) * 2;

    const uint32_t uQh = smem_u32(sQh), uQl = smem_u32(sQl);
    const uint32_t uKh = smem_u32(sKh), uKl = smem_u32(sKl);
    const uint32_t uVh = smem_u32(sVh), uVl = smem_u32(sVl);

    const int ktiles = 2*qt + 2;
    for (int kt = 0; kt < ktiles; kt++) {
        const int kb = kt * 64;
        const size_t koff = ((size_t)bh * TLEN + kb) * 64;
        const size_t voff = (size_t)bh * 64 * TLEN + kb;
#pragma unroll
        for (int i = 0; i < 4; i++) {
            int idx = tid + i*128;
            int r = idx >> 3, c = (idx & 7) * 8;
            *reinterpret_cast<uint4*>(sKh + r*ALD + c) =
                *reinterpret_cast<const uint4*>(Kh + koff + (size_t)r*64 + c);
            *reinterpret_cast<uint4*>(sKl + r*ALD + c) =
                *reinterpret_cast<const uint4*>(Kl + koff + (size_t)r*64 + c);
            *reinterpret_cast<uint4*>(sVh + r*ALD + c) =
                *reinterpret_cast<const uint4*>(Vh + voff + (size_t)r*TLEN + c);
            *reinterpret_cast<uint4*>(sVl + r*ALD + c) =
                *reinterpret_cast<const uint4*>(Vl + voff + (size_t)r*TLEN + c);
        }
        __syncthreads();

        if (kb <= q0 + 31) {   // warp has at least one unmasked row
            // ---- S = Q K^T (3 split passes) ----
            float s[2][8][4];
#pragma unroll
            for (int mt = 0; mt < 2; mt++)
#pragma unroll
                for (int nt = 0; nt < 8; nt++)
#pragma unroll
                    for (int e = 0; e < 4; e++) s[mt][nt][e] = 0.0f;

#pragma unroll
            for (int kk = 0; kk < 64; kk += 16) {
                uint32_t qh[2][4], ql[2][4];
#pragma unroll
                for (int mt = 0; mt < 2; mt++) {
                    uint32_t off = ((wm*32 + mt*16 + a_r) * ALD + kk + a_c) * 2;
                    ldsm_x4(qh[mt][0], qh[mt][1], qh[mt][2], qh[mt][3], uQh + off);
                    ldsm_x4(ql[mt][0], ql[mt][1], ql[mt][2], ql[mt][3], uQl + off);
                }
                uint32_t kh[4][4], kl[4][4];
#pragma unroll
                for (int nt2 = 0; nt2 < 4; nt2++) {
                    uint32_t off = ((nt2*16 + b_r) * ALD + kk + b_c) * 2;
                    ldsm_x4(kh[nt2][0], kh[nt2][1], kh[nt2][2], kh[nt2][3], uKh + off);
                    ldsm_x4(kl[nt2][0], kl[nt2][1], kl[nt2][2], kl[nt2][3], uKl + off);
                }
#pragma unroll
                for (int mt = 0; mt < 2; mt++) {
#pragma unroll
                    for (int nt2 = 0; nt2 < 4; nt2++) {
                        float* d0 = s[mt][2*nt2];
                        float* d1 = s[mt][2*nt2+1];
                        mma_bf16(d0[0],d0[1],d0[2],d0[3],
                                 qh[mt][0],qh[mt][1],qh[mt][2],qh[mt][3],
                                 kh[nt2][0],kh[nt2][1]);
                        mma_bf16(d1[0],d1[1],d1[2],d1[3],
                                 qh[mt][0],qh[mt][1],qh[mt][2],qh[mt][3],
                                 kh[nt2][2],kh[nt2][3]);
                        mma_bf16(d0[0],d0[1],d0[2],d0[3],
                                 qh[mt][0],qh[mt][1],qh[mt][2],qh[mt][3],
                                 kl[nt2][0],kl[nt2][1]);
                        mma_bf16(d1[0],d1[1],d1[2],d1[3],
                                 qh[mt][0],qh[mt][1],qh[mt][2],qh[mt][3],
                                 kl[nt2][2],kl[nt2][3]);
                        mma_bf16(d0[0],d0[1],d0[2],d0[3],
                                 ql[mt][0],ql[mt][1],ql[mt][2],ql[mt][3],
                                 kh[nt2][0],kh[nt2][1]);
                        mma_bf16(d1[0],d1[1],d1[2],d1[3],
                                 ql[mt][0],ql[mt][1],ql[mt][2],ql[mt][3],
                                 kh[nt2][2],kh[nt2][3]);
                    }
                }
            }

            // ---- causal mask (diagonal tiles only) ----
            if (kb + 63 > q0) {
#pragma unroll
                for (int mt = 0; mt < 2; mt++) {
                    const int r0 = q0 + mt*16 + lr;
#pragma unroll
                    for (int nt = 0; nt < 8; nt++) {
                        const int c0 = kb + nt*8 + lc2;
                        if (c0     > r0)     s[mt][nt][0] = NEG_INF;
                        if (c0 + 1 > r0)     s[mt][nt][1] = NEG_INF;
                        if (c0     > r0 + 8) s[mt][nt][2] = NEG_INF;
                        if (c0 + 1 > r0 + 8) s[mt][nt][3] = NEG_INF;
                    }
                }
            }

            // ---- online softmax on fragments ----
            float alpha[4];
#pragma unroll
            for (int mt = 0; mt < 2; mt++) {
#pragma unroll
                for (int hh = 0; hh < 2; hh++) {
                    const int e0 = hh*2;
                    const int id = mt*2 + hh;
                    float mx = NEG_INF;
#pragma unroll
                    for (int nt = 0; nt < 8; nt++)
                        mx = fmaxf(mx, fmaxf(s[mt][nt][e0], s[mt][nt][e0+1]));
                    mx = fmaxf(mx, __shfl_xor_sync(0xffffffffu, mx, 1));
                    mx = fmaxf(mx, __shfl_xor_sync(0xffffffffu, mx, 2));
                    const float mnew = fmaxf(mrow[id], mx);
                    const float al = ex2f(mrow[id] - mnew);
                    mrow[id] = mnew;
                    float ls = 0.0f;
#pragma unroll
                    for (int nt = 0; nt < 8; nt++) {
                        float p0 = ex2f(s[mt][nt][e0]   - mnew);
                        float p1 = ex2f(s[mt][nt][e0+1] - mnew);
                        s[mt][nt][e0]   = p0;
                        s[mt][nt][e0+1] = p1;
                        ls += p0 + p1;
                    }
                    ls += __shfl_xor_sync(0xffffffffu, ls, 1);
                    ls += __shfl_xor_sync(0xffffffffu, ls, 2);
                    lrow[id] = lrow[id] * al + ls;
                    alpha[id] = al;
                }
            }
#pragma unroll
            for (int mt = 0; mt < 2; mt++)
#pragma unroll
                for (int nt = 0; nt < 8; nt++) {
                    o[mt][nt][0] *= alpha[mt*2];
                    o[mt][nt][1] *= alpha[mt*2];
                    o[mt][nt][2] *= alpha[mt*2+1];
                    o[mt][nt][3] *= alpha[mt*2+1];
                }

            // ---- O += P V (3 split passes) ----
#pragma unroll
            for (int kk = 0; kk < 4; kk++) {
                uint32_t vh[4][4], vl[4][4];
#pragma unroll
                for (int nt2 = 0; nt2 < 4; nt2++) {
                    uint32_t off = ((nt2*16 + b_r) * ALD + kk*16 + b_c) * 2;
                    ldsm_x4(vh[nt2][0], vh[nt2][1], vh[nt2][2], vh[nt2][3], uVh + off);
                    ldsm_x4(vl[nt2][0], vl[nt2][1], vl[nt2][2], vl[nt2][3], uVl + off);
                }
#pragma unroll
                for (int mt = 0; mt < 2; mt++) {
                    uint32_t ph[4], pl[4];
                    split2(s[mt][2*kk][0],   s[mt][2*kk][1],   ph[0], pl[0]);
                    split2(s[mt][2*kk][2],   s[mt][2*kk][3],   ph[1], pl[1]);
                    split2(s[mt][2*kk+1][0], s[mt][2*kk+1][1], ph[2], pl[2]);
                    split2(s[mt][2*kk+1][2], s[mt][2*kk+1][3], ph[3], pl[3]);
#pragma unroll
                    for (int nt2 = 0; nt2 < 4; nt2++) {
                        float* d0 = o[mt][2*nt2];
                        float* d1 = o[mt][2*nt2+1];
                        mma_bf16(d0[0],d0[1],d0[2],d0[3],
                                 ph[0],ph[1],ph[2],ph[3],
                                 vh[nt2][0],vh[nt2][1]);
                        mma_bf16(d1[0],d1[1],d1[2],d1[3],
                                 ph[0],ph[1],ph[2],ph[3],
                                 vh[nt2][2],vh[nt2][3]);
                        mma_bf16(d0[0],d0[1],d0[2],d0[3],
                                 ph[0],ph[1],ph[2],ph[3],
                                 vl[nt2][0],vl[nt2][1]);
                        mma_bf16(d1[0],d1[1],d1[2],d1[3],
                                 ph[0],ph[1],ph[2],ph[3],
                                 vl[nt2][2],vl[nt2][3]);
                        mma_bf16(d0[0],d0[1],d0[2],d0[3],
                                 pl[0],pl[1],pl[2],pl[3],
                                 vh[nt2][0],vh[nt2][1]);
                        mma_bf16(d1[0],d1[1],d1[2],d1[3],
                                 pl[0],pl[1],pl[2],pl[3],
                                 vh[nt2][2],vh[nt2][3]);
                    }
                }
            }
        }
        __syncthreads();
    }

    // ---- normalize + write ----
#pragma unroll
    for (int mt = 0; mt < 2; mt++) {
#pragma unroll
        for (int hh = 0; hh < 2; hh++) {
            const float inv = 1.0f / lrow[mt*2 + hh];
            const int row = qt*128 + wm*32 + mt*16 + lr + hh*8;
            float* yp = y + ((size_t)(b*TLEN + row))*CDIM + h*64;
#pragma unroll
            for (int nt = 0; nt < 8; nt++) {
                float2 v;
                v.x = o[mt][nt][hh*2]   * inv;
                v.y = o[mt][nt][hh*2+1] * inv;
                *reinterpret_cast<float2*>(yp + nt*8 + lc2) = v;
            }
        }
    }
}

// ---------------------------------------------------------------------------
// Launch
// ---------------------------------------------------------------------------
extern "C" void kernel_launch(void* const* d_in, const int* in_sizes, int n_in,
                              void* d_out, int out_size)
{
    (void)in_sizes; (void)n_in; (void)out_size;
    const float* x      = (const float*)d_in[0];
    const float* W_attn = (const float*)d_in[1];
    const float* b_attn = (const float*)d_in[2];
    const float* W_proj = (const float*)d_in[3];
    const float* b_proj = (const float*)d_in[4];
    float* out = (float*)d_out;

    float *qkv_ptr, *y_ptr;
    __nv_bfloat16 *ah, *al, *wah, *wal, *wph, *wpl;
    __nv_bfloat16 *qh2, *ql2, *kh2, *kl2, *vth, *vtl;
    cudaGetSymbolAddress((void**)&qkv_ptr, g_qkv);
    cudaGetSymbolAddress((void**)&y_ptr,   g_y);
    cudaGetSymbolAddress((void**)&ah,  g_ah);
    cudaGetSymbolAddress((void**)&al,  g_al);
    cudaGetSymbolAddress((void**)&wah, g_wah);
    cudaGetSymbolAddress((void**)&wal, g_wal);
    cudaGetSymbolAddress((void**)&wph, g_wph);
    cudaGetSymbolAddress((void**)&wpl, g_wpl);
    cudaGetSymbolAddress((void**)&qh2, g_qh2);
    cudaGetSymbolAddress((void**)&ql2, g_ql2);
    cudaGetSymbolAddress((void**)&kh2, g_kh2);
    cudaGetSymbolAddress((void**)&kl2, g_kl2);
    cudaGetSymbolAddress((void**)&vth, g_vth);
    cudaGetSymbolAddress((void**)&vtl, g_vtl);

    static bool attr_set = false;
    if (!attr_set) {
        cudaFuncSetAttribute(gemm_hmma_kernel,
                             cudaFuncAttributeMaxDynamicSharedMemorySize,
                             GEMM_SMEM_BYTES);
        cudaFuncSetAttribute(attn_mma_kernel,
                             cudaFuncAttributeMaxDynamicSharedMemorySize,
                             ATTN_SMEM_BYTES);
        attr_set = true;
    }

    const int M = MROWS;

    // Prep: split x; transpose+split weights
    {
        int n4 = M * CDIM / 4;
        split_kernel<<<(n4 + 255)/256, 256>>>(x, ah, al, n4);
        dim3 tb(32, 8);
        transpose_split_kernel<<<dim3(3*CDIM/32, CDIM/32), tb>>>(W_attn, wah, wal, CDIM, 3*CDIM);
        transpose_split_kernel<<<dim3(CDIM/32, CDIM/32), tb>>>(W_proj, wph, wpl, CDIM, CDIM);
    }

    // 1) QKV GEMM
    gemm_hmma_kernel<<<dim3(3*CDIM/128, M/128), 256, GEMM_SMEM_BYTES>>>(
        ah, al, wah, wal, b_attn, qkv_ptr, 3*CDIM, CDIM);

    // 2) attention prep: split+reshape Q,K ; transpose+split V
    {
        int n = BSZ*TLEN*2*HN*16;
        split_qk_kernel<<<(n + 255)/256, 256>>>(qkv_ptr, qh2, ql2, kh2, kl2);
        dim3 tb(32, 8);
        transpose_split_v_kernel<<<dim3(BSZ*HN, TLEN/32, 2), tb>>>(qkv_ptr, vth, vtl);
    }

    // 3) flash attention (HMMA)
    attn_mma_kernel<<<dim3(TLEN/128, BSZ*HN), 128, ATTN_SMEM_BYTES>>>(
        qh2, ql2, kh2, kl2, vth, vtl, y_ptr);

    // 4) split y, proj GEMM
    {
        int n4 = M * CDIM / 4;
        split_kernel<<<(n4 + 255)/256, 256>>>(y_ptr, ah, al, n4);
    }
    gemm_hmma_kernel<<<dim3(CDIM/128, M/128), 256, GEMM_SMEM_BYTES>>>(
        ah, al, wph, wpl, b_proj, out, CDIM, CDIM);
}

// round 5
// speedup vs baseline: 3.2843x; 1.0873x over previous
#include <cuda_runtime.h>
#include <cuda_bf16.h>
#include <math.h>
#include <stdint.h>

// Problem constants
#define BSZ 4
#define TLEN 2048
#define CDIM 768
#define HN 12
#define DH 64
#define ROWSTRIDE (3*CDIM)   // 2304
#define MROWS (BSZ*TLEN)     // 8192

// ---------------------------------------------------------------------------
// Scratch
// ---------------------------------------------------------------------------
__device__ float g_qkv[(size_t)BSZ*TLEN*3*CDIM];           // [B,T,3C]
__device__ float g_y  [(size_t)BSZ*TLEN*CDIM];             // [B,T,C]
__device__ __nv_bfloat16 g_ah[(size_t)MROWS*CDIM];
__device__ __nv_bfloat16 g_al[(size_t)MROWS*CDIM];
__device__ __nv_bfloat16 g_wah[(size_t)(3*CDIM)*CDIM];
__device__ __nv_bfloat16 g_wal[(size_t)(3*CDIM)*CDIM];
__device__ __nv_bfloat16 g_wph[(size_t)CDIM*CDIM];
__device__ __nv_bfloat16 g_wpl[(size_t)CDIM*CDIM];
#define AHT ((size_t)BSZ*HN*TLEN*DH)
__device__ __nv_bfloat16 g_qh2[AHT];
__device__ __nv_bfloat16 g_ql2[AHT];
__device__ __nv_bfloat16 g_kh2[AHT];
__device__ __nv_bfloat16 g_kl2[AHT];
__device__ __nv_bfloat16 g_vth[AHT];
__device__ __nv_bfloat16 g_vtl[AHT];

// ---------------------------------------------------------------------------
// helpers
// ---------------------------------------------------------------------------
__device__ __forceinline__ uint32_t smem_u32(const void* p) {
    uint32_t a;
    asm("{ .reg .u64 t; cvta.to.shared.u64 t, %1; cvt.u32.u64 %0, t; }"
        : "=r"(a) : "l"(p));
    return a;
}
__device__ __forceinline__ void ldsm_x4(uint32_t& r0, uint32_t& r1,
                                        uint32_t& r2, uint32_t& r3,
                                        uint32_t addr) {
    asm volatile("ldmatrix.sync.aligned.m8n8.x4.shared.b16 {%0,%1,%2,%3}, [%4];"
                 : "=r"(r0), "=r"(r1), "=r"(r2), "=r"(r3) : "r"(addr));
}
__device__ __forceinline__ void mma_bf16(float& d0, float& d1, float& d2, float& d3,
                                         uint32_t a0, uint32_t a1, uint32_t a2, uint32_t a3,
                                         uint32_t b0, uint32_t b1) {
    asm volatile(
        "mma.sync.aligned.m16n8k16.row.col.f32.bf16.bf16.f32 "
        "{%0,%1,%2,%3}, {%4,%5,%6,%7}, {%8,%9}, {%0,%1,%2,%3};"
        : "+f"(d0), "+f"(d1), "+f"(d2), "+f"(d3)
        : "r"(a0), "r"(a1), "r"(a2), "r"(a3), "r"(b0), "r"(b1));
}
__device__ __forceinline__ float ex2f(float x) {
    float r; asm("ex2.approx.ftz.f32 %0, %1;" : "=f"(r) : "f"(x)); return r;
}
__device__ __forceinline__ void split2(float x, float y, uint32_t& hi, uint32_t& lo) {
    __nv_bfloat162 h = __floats2bfloat162_rn(x, y);
    __nv_bfloat162 l = __floats2bfloat162_rn(x - __low2float(h), y - __high2float(h));
    hi = *reinterpret_cast<uint32_t*>(&h);
    lo = *reinterpret_cast<uint32_t*>(&l);
}
__device__ __forceinline__ void cp_async16(uint32_t dst, const void* src) {
    asm volatile("cp.async.ca.shared.global [%0], [%1], 16;"
                 :: "r"(dst), "l"(src));
}

// ---------------------------------------------------------------------------
// fp32 -> (hi, lo) bf16 split, elementwise
// ---------------------------------------------------------------------------
__global__ __launch_bounds__(256) void split_kernel(
    const float* __restrict__ in, __nv_bfloat16* __restrict__ hi,
    __nv_bfloat16* __restrict__ lo, int n4)
{
    int i = blockIdx.x * blockDim.x + threadIdx.x;
    if (i >= n4) return;
    float4 v = reinterpret_cast<const float4*>(in)[i];
    __nv_bfloat162 h01 = __floats2bfloat162_rn(v.x, v.y);
    __nv_bfloat162 h23 = __floats2bfloat162_rn(v.z, v.w);
    reinterpret_cast<__nv_bfloat162*>(hi)[i*2]   = h01;
    reinterpret_cast<__nv_bfloat162*>(hi)[i*2+1] = h23;
    __nv_bfloat162 l01 = __floats2bfloat162_rn(v.x - __low2float(h01), v.y - __high2float(h01));
    __nv_bfloat162 l23 = __floats2bfloat162_rn(v.z - __low2float(h23), v.w - __high2float(h23));
    reinterpret_cast<__nv_bfloat162*>(lo)[i*2]   = l01;
    reinterpret_cast<__nv_bfloat162*>(lo)[i*2+1] = l23;
}

// ---------------------------------------------------------------------------
// W[K,N] fp32 -> Wt hi/lo [N,K] bf16 (transpose + split)
// ---------------------------------------------------------------------------
__global__ __launch_bounds__(256) void transpose_split_kernel(
    const float* __restrict__ W, __nv_bfloat16* __restrict__ th,
    __nv_bfloat16* __restrict__ tl, int K, int N)
{
    __shared__ float t[32][33];
    const int n0 = blockIdx.x * 32, k0 = blockIdx.y * 32;
    const int tx = threadIdx.x, ty0 = threadIdx.y;
#pragma unroll
    for (int i = 0; i < 4; i++) {
        int ty = ty0 + i*8;
        t[ty][tx] = W[(size_t)(k0 + ty) * N + n0 + tx];
    }
    __syncthreads();
#pragma unroll
    for (int i = 0; i < 4; i++) {
        int ty = ty0 + i*8;
        float v = t[tx][ty];
        __nv_bfloat16 h = __float2bfloat16(v);
        th[(size_t)(n0 + ty) * K + k0 + tx] = h;
        tl[(size_t)(n0 + ty) * K + k0 + tx] =
            __float2bfloat16(v - __bfloat162float(h));
    }
}

// ---------------------------------------------------------------------------
// qkv [B,T,3C] -> Q hi/lo (scaled by 0.125*log2e), K hi/lo as [B*H, T, 64]
// ---------------------------------------------------------------------------
__global__ __launch_bounds__(256) void split_qk_kernel(
    const float* __restrict__ qkv,
    __nv_bfloat16* __restrict__ Qh, __nv_bfloat16* __restrict__ Ql,
    __nv_bfloat16* __restrict__ Kh, __nv_bfloat16* __restrict__ Kl)
{
    int i = blockIdx.x * blockDim.x + threadIdx.x;
    if (i >= BSZ*TLEN*2*HN*16) return;
    int j = i;
    int d4 = j & 15; j >>= 4;
    int h  = j % HN; j /= HN;
    int s  = j & 1;  j >>= 1;
    int t  = j & (TLEN-1); j >>= 11;
    int b  = j;
    const float4 v = *reinterpret_cast<const float4*>(
        qkv + ((size_t)(b*TLEN + t))*ROWSTRIDE + s*CDIM + h*64 + d4*4);
    const float sc = s ? 1.0f : 0.18033688011112042f;  // 0.125*log2(e)
    float x0 = v.x*sc, x1 = v.y*sc, x2 = v.z*sc, x3 = v.w*sc;
    __nv_bfloat162 h01 = __floats2bfloat162_rn(x0, x1);
    __nv_bfloat162 h23 = __floats2bfloat162_rn(x2, x3);
    __nv_bfloat162 l01 = __floats2bfloat162_rn(x0 - __low2float(h01), x1 - __high2float(h01));
    __nv_bfloat162 l23 = __floats2bfloat162_rn(x2 - __low2float(h23), x3 - __high2float(h23));
    size_t dst = (((size_t)(b*HN + h))*TLEN + t)*64 + d4*4;
    __nv_bfloat16* H = s ? Kh : Qh;
    __nv_bfloat16* L = s ? Kl : Ql;
    *reinterpret_cast<__nv_bfloat162*>(H + dst)     = h01;
    *reinterpret_cast<__nv_bfloat162*>(H + dst + 2) = h23;
    *reinterpret_cast<__nv_bfloat162*>(L + dst)     = l01;
    *reinterpret_cast<__nv_bfloat162*>(L + dst + 2) = l23;
}

// ---------------------------------------------------------------------------
// V from qkv -> transposed [B*H, 64, T] hi/lo bf16
// ---------------------------------------------------------------------------
__global__ __launch_bounds__(256) void transpose_split_v_kernel(
    const float* __restrict__ qkv,
    __nv_bfloat16* __restrict__ Vh, __nv_bfloat16* __restrict__ Vl)
{
    __shared__ float t[32][33];
    const int bh = blockIdx.x;
    const int t0 = blockIdx.y * 32;
    const int d0 = blockIdx.z * 32;
    const int b = bh / HN, h = bh % HN;
    const int tx = threadIdx.x, ty0 = threadIdx.y;
#pragma unroll
    for (int i = 0; i < 4; i++) {
        int ty = ty0 + i*8;
        t[ty][tx] = qkv[((size_t)(b*TLEN + t0 + ty))*ROWSTRIDE + 2*CDIM + h*64 + d0 + tx];
    }
    __syncthreads();
#pragma unroll
    for (int i = 0; i < 4; i++) {
        int dy = ty0 + i*8;
        float v = t[tx][dy];
        __nv_bfloat16 hi = __float2bfloat16(v);
        size_t dst = ((size_t)bh*64 + d0 + dy)*TLEN + t0 + tx;
        Vh[dst] = hi;
        Vl[dst] = __float2bfloat16(v - __bfloat162float(hi));
    }
}

// ---------------------------------------------------------------------------
// HMMA split-bf16 GEMM v2: 128x128 CTA tile, 4 warps (2x2), warp tile 64x64,
// BK=32, cp.async 2-stage pipeline. grid (N/128, M/128), 128 threads.
// ---------------------------------------------------------------------------
#define LDP 40
#define TILE_ELEMS (128*LDP)        // 5120
#define TILE_BYTES (TILE_ELEMS*2)   // 10240
#define STAGE_BYTES (4*TILE_BYTES)  // 40960 (Ah, Al, Bh, Bl)
#define GEMM_SMEM_BYTES (2*STAGE_BYTES)   // 81920

__global__ __launch_bounds__(128) void gemm_hmma_kernel(
    const __nv_bfloat16* __restrict__ Ah, const __nv_bfloat16* __restrict__ Al,
    const __nv_bfloat16* __restrict__ Bh, const __nv_bfloat16* __restrict__ Bl,
    const float* __restrict__ bias, float* __restrict__ Cm,
    int N, int K)
{
    extern __shared__ __nv_bfloat16 smem[];
    const uint32_t sbase = smem_u32(smem);
    const int tid  = threadIdx.x;
    const int wid  = tid >> 5;
    const int lane = tid & 31;
    const int bx = blockIdx.x, by = blockIdx.y;
    const int wm = wid & 1;          // M offset 64*wm
    const int wn = wid >> 1;         // N offset 64*wn

    const __nv_bfloat16* srcs[4];
    srcs[0] = Ah + (size_t)(by * 128) * K;
    srcs[1] = Al + (size_t)(by * 128) * K;
    srcs[2] = Bh + (size_t)(bx * 128) * K;
    srcs[3] = Bl + (size_t)(bx * 128) * K;

    // per-thread load coords: 512 x 16B per tile / 128 thr = 4 each
    // idx = tid + q*128 ; row = idx>>2 ; col = (idx&3)*8
    const int lrw = tid >> 2;             // base row for q=0
    const int lcl = (tid & 3) * 8;

    float d[4][8][4];
#pragma unroll
    for (int mt = 0; mt < 4; mt++)
#pragma unroll
        for (int nt = 0; nt < 8; nt++)
#pragma unroll
            for (int e = 0; e < 4; e++) d[mt][nt][e] = 0.0f;

    const int KC = K / 32;

    auto load_stage = [&](int kc, int buf) {
        const int k0 = kc * 32;
        const uint32_t sdst = sbase + (uint32_t)buf * STAGE_BYTES;
#pragma unroll
        for (int t = 0; t < 4; t++) {
            const __nv_bfloat16* base = srcs[t] + k0;
#pragma unroll
            for (int q = 0; q < 4; q++) {
                const int r = lrw + q * 32;
                const uint32_t dst = sdst + (uint32_t)t * TILE_BYTES
                                   + (uint32_t)(r * LDP + lcl) * 2;
                cp_async16(dst, base + (size_t)r * K + lcl);
            }
        }
        asm volatile("cp.async.commit_group;" ::: "memory");
    };

    load_stage(0, 0);

    const int a_r = (lane & 15);
    const int a_c = (lane >> 4) * 8;
    const int b_r = ((lane >> 4) & 1) * 8 + (lane & 7);
    const int b_c = ((lane >> 3) & 1) * 8;

    for (int c = 0; c < KC; c++) {
        const int cur = c & 1;
        if (c + 1 < KC) {
            load_stage(c + 1, cur ^ 1);
            asm volatile("cp.async.wait_group 1;" ::: "memory");
        } else {
            asm volatile("cp.async.wait_group 0;" ::: "memory");
        }
        __syncthreads();

        const uint32_t sAh = sbase + (uint32_t)cur * STAGE_BYTES;
        const uint32_t sAl = sAh + TILE_BYTES;
        const uint32_t sBh = sAl + TILE_BYTES;
        const uint32_t sBl = sBh + TILE_BYTES;

#pragma unroll
        for (int kk = 0; kk < 32; kk += 16) {
            uint32_t ah[4][4], al[4][4];
#pragma unroll
            for (int mt = 0; mt < 4; mt++) {
                uint32_t off = ((wm*64 + mt*16 + a_r) * LDP + kk + a_c) * 2;
                ldsm_x4(ah[mt][0], ah[mt][1], ah[mt][2], ah[mt][3], sAh + off);
                ldsm_x4(al[mt][0], al[mt][1], al[mt][2], al[mt][3], sAl + off);
            }
            uint32_t bh[4][4], bl[4][4];
#pragma unroll
            for (int nt2 = 0; nt2 < 4; nt2++) {
                uint32_t off = ((wn*64 + nt2*16 + b_r) * LDP + kk + b_c) * 2;
                ldsm_x4(bh[nt2][0], bh[nt2][1], bh[nt2][2], bh[nt2][3], sBh + off);
                ldsm_x4(bl[nt2][0], bl[nt2][1], bl[nt2][2], bl[nt2][3], sBl + off);
            }
#pragma unroll
            for (int mt = 0; mt < 4; mt++) {
#pragma unroll
                for (int nt2 = 0; nt2 < 4; nt2++) {
                    float* d0 = d[mt][2*nt2];
                    float* d1 = d[mt][2*nt2+1];
                    mma_bf16(d0[0],d0[1],d0[2],d0[3],
                             ah[mt][0],ah[mt][1],ah[mt][2],ah[mt][3],
                             bh[nt2][0],bh[nt2][1]);
                    mma_bf16(d1[0],d1[1],d1[2],d1[3],
                             ah[mt][0],ah[mt][1],ah[mt][2],ah[mt][3],
                             bh[nt2][2],bh[nt2][3]);
                    mma_bf16(d0[0],d0[1],d0[2],d0[3],
                             ah[mt][0],ah[mt][1],ah[mt][2],ah[mt][3],
                             bl[nt2][0],bl[nt2][1]);
                    mma_bf16(d1[0],d1[1],d1[2],d1[3],
                             ah[mt][0],ah[mt][1],ah[mt][2],ah[mt][3],
                             bl[nt2][2],bl[nt2][3]);
                    mma_bf16(d0[0],d0[1],d0[2],d0[3],
                             al[mt][0],al[mt][1],al[mt][2],al[mt][3],
                             bh[nt2][0],bh[nt2][1]);
                    mma_bf16(d1[0],d1[1],d1[2],d1[3],
                             al[mt][0],al[mt][1],al[mt][2],al[mt][3],
                             bh[nt2][2],bh[nt2][3]);
                }
            }
        }
        __syncthreads();
    }

    // ------------------- epilogue: bias + store -------------------
    const int row_base = by * 128 + wm * 64;
    const int col_base = bx * 128 + wn * 64;
    const int lr = lane >> 2;
    const int lc = (lane & 3) * 2;
#pragma unroll
    for (int mt = 0; mt < 4; mt++) {
        const int r0 = row_base + mt*16 + lr;
        const int r1 = r0 + 8;
#pragma unroll
        for (int nt = 0; nt < 8; nt++) {
            const int cc = col_base + nt*8 + lc;
            float b0 = __ldg(bias + cc), b1 = __ldg(bias + cc + 1);
            float2 o0; o0.x = d[mt][nt][0] + b0; o0.y = d[mt][nt][1] + b1;
            float2 o1; o1.x = d[mt][nt][2] + b0; o1.y = d[mt][nt][3] + b1;
            *reinterpret_cast<float2*>(Cm + (size_t)r0 * N + cc) = o0;
            *reinterpret_cast<float2*>(Cm + (size_t)r1 * N + cc) = o1;
        }
    }
}

// ---------------------------------------------------------------------------
// HMMA flash attention (causal) — unchanged from round 4 (passing).
// ---------------------------------------------------------------------------
#define ALD 72
#define ATTN_SMEM_BYTES ((2*128*ALD + 4*64*ALD) * 2)   // 73728

__global__ __launch_bounds__(128) void attn_mma_kernel(
    const __nv_bfloat16* __restrict__ Qh, const __nv_bfloat16* __restrict__ Ql,
    const __nv_bfloat16* __restrict__ Kh, const __nv_bfloat16* __restrict__ Kl,
    const __nv_bfloat16* __restrict__ Vh, const __nv_bfloat16* __restrict__ Vl,
    float* __restrict__ y)
{
    extern __shared__ __nv_bfloat16 sab[];
    __nv_bfloat16* sQh = sab;
    __nv_bfloat16* sQl = sQh + 128*ALD;
    __nv_bfloat16* sKh = sQl + 128*ALD;
    __nv_bfloat16* sKl = sKh + 64*ALD;
    __nv_bfloat16* sVh = sKl + 64*ALD;
    __nv_bfloat16* sVl = sVh + 64*ALD;

    const int tid = threadIdx.x, lane = tid & 31, wm = tid >> 5;
    const int qt = blockIdx.x, bh = blockIdx.y;
    const int b = bh / HN, h = bh % HN;

    const size_t qoff = ((size_t)bh * TLEN + (size_t)qt*128) * 64;
#pragma unroll
    for (int i = 0; i < 8; i++) {
        int idx = tid + i*128;
        int r = idx >> 3, c = (idx & 7) * 8;
        *reinterpret_cast<uint4*>(sQh + r*ALD + c) =
            *reinterpret_cast<const uint4*>(Qh + qoff + (size_t)r*64 + c);
        *reinterpret_cast<uint4*>(sQl + r*ALD + c) =
            *reinterpret_cast<const uint4*>(Ql + qoff + (size_t)r*64 + c);
    }

    float o[2][8][4];
#pragma unroll
    for (int mt = 0; mt < 2; mt++)
#pragma unroll
        for (int nt = 0; nt < 8; nt++)
#pragma unroll
            for (int e = 0; e < 4; e++) o[mt][nt][e] = 0.0f;

    const float NEG_INF = __int_as_float(0xff800000);
    float mrow[4] = {NEG_INF, NEG_INF, NEG_INF, NEG_INF};
    float lrow[4] = {0.0f, 0.0f, 0.0f, 0.0f};

    const int q0 = qt*128 + wm*32;
    const int a_r = lane & 15, a_c = (lane >> 4) * 8;
    const int b_r = ((lane >> 4) & 1) * 8 + (lane & 7);
    const int b_c = ((lane >> 3) & 1) * 8;
    const int lr = lane >> 2, lc2 = (lane & 3) * 2;

    const uint32_t uQh = smem_u32(sQh), uQl = smem_u32(sQl);
    const uint32_t uKh = smem_u32(sKh), uKl = smem_u32(sKl);
    const uint32_t uVh = smem_u32(sVh), uVl = smem_u32(sVl);

    const int ktiles = 2*qt + 2;
    for (int kt = 0; kt < ktiles; kt++) {
        const int kb = kt * 64;
        const size_t koff = ((size_t)bh * TLEN + kb) * 64;
        const size_t voff = (size_t)bh * 64 * TLEN + kb;
#pragma unroll
        for (int i = 0; i < 4; i++) {
            int idx = tid + i*128;
            int r = idx >> 3, c = (idx & 7) * 8;
            *reinterpret_cast<uint4*>(sKh + r*ALD + c) =
                *reinterpret_cast<const uint4*>(Kh + koff + (size_t)r*64 + c);
            *reinterpret_cast<uint4*>(sKl + r*ALD + c) =
                *reinterpret_cast<const uint4*>(Kl + koff + (size_t)r*64 + c);
            *reinterpret_cast<uint4*>(sVh + r*ALD + c) =
                *reinterpret_cast<const uint4*>(Vh + voff + (size_t)r*TLEN + c);
            *reinterpret_cast<uint4*>(sVl + r*ALD + c) =
                *reinterpret_cast<const uint4*>(Vl + voff + (size_t)r*TLEN + c);
        }
        __syncthreads();

        if (kb <= q0 + 31) {
            float s[2][8][4];
#pragma unroll
            for (int mt = 0; mt < 2; mt++)
#pragma unroll
                for (int nt = 0; nt < 8; nt++)
#pragma unroll
                    for (int e = 0; e < 4; e++) s[mt][nt][e] = 0.0f;

#pragma unroll
            for (int kk = 0; kk < 64; kk += 16) {
                uint32_t qh[2][4], ql[2][4];
#pragma unroll
                for (int mt = 0; mt < 2; mt++) {
                    uint32_t off = ((wm*32 + mt*16 + a_r) * ALD + kk + a_c) * 2;
                    ldsm_x4(qh[mt][0], qh[mt][1], qh[mt][2], qh[mt][3], uQh + off);
                    ldsm_x4(ql[mt][0], ql[mt][1], ql[mt][2], ql[mt][3], uQl + off);
                }
                uint32_t kh[4][4], kl[4][4];
#pragma unroll
                for (int nt2 = 0; nt2 < 4; nt2++) {
                    uint32_t off = ((nt2*16 + b_r) * ALD + kk + b_c) * 2;
                    ldsm_x4(kh[nt2][0], kh[nt2][1], kh[nt2][2], kh[nt2][3], uKh + off);
                    ldsm_x4(kl[nt2][0], kl[nt2][1], kl[nt2][2], kl[nt2][3], uKl + off);
                }
#pragma unroll
                for (int mt = 0; mt < 2; mt++) {
#pragma unroll
                    for (int nt2 = 0; nt2 < 4; nt2++) {
                        float* d0 = s[mt][2*nt2];
                        float* d1 = s[mt][2*nt2+1];
                        mma_bf16(d0[0],d0[1],d0[2],d0[3],
                                 qh[mt][0],qh[mt][1],qh[mt][2],qh[mt][3],
                                 kh[nt2][0],kh[nt2][1]);
                        mma_bf16(d1[0],d1[1],d1[2],d1[3],
                                 qh[mt][0],qh[mt][1],qh[mt][2],qh[mt][3],
                                 kh[nt2][2],kh[nt2][3]);
                        mma_bf16(d0[0],d0[1],d0[2],d0[3],
                                 qh[mt][0],qh[mt][1],qh[mt][2],qh[mt][3],
                                 kl[nt2][0],kl[nt2][1]);
                        mma_bf16(d1[0],d1[1],d1[2],d1[3],
                                 qh[mt][0],qh[mt][1],qh[mt][2],qh[mt][3],
                                 kl[nt2][2],kl[nt2][3]);
                        mma_bf16(d0[0],d0[1],d0[2],d0[3],
                                 ql[mt][0],ql[mt][1],ql[mt][2],ql[mt][3],
                                 kh[nt2][0],kh[nt2][1]);
                        mma_bf16(d1[0],d1[1],d1[2],d1[3],
                                 ql[mt][0],ql[mt][1],ql[mt][2],ql[mt][3],
                                 kh[nt2][2],kh[nt2][3]);
                    }
                }
            }

            if (kb + 63 > q0) {
#pragma unroll
                for (int mt = 0; mt < 2; mt++) {
                    const int r0 = q0 + mt*16 + lr;
#pragma unroll
                    for (int nt = 0; nt < 8; nt++) {
                        const int c0 = kb + nt*8 + lc2;
                        if (c0     > r0)     s[mt][nt][0] = NEG_INF;
                        if (c0 + 1 > r0)     s[mt][nt][1] = NEG_INF;
                        if (c0     > r0 + 8) s[mt][nt][2] = NEG_INF;
                        if (c0 + 1 > r0 + 8) s[mt][nt][3] = NEG_INF;
                    }
                }
            }

            float alpha[4];
#pragma unroll
            for (int mt = 0; mt < 2; mt++) {
#pragma unroll
                for (int hh = 0; hh < 2; hh++) {
                    const int e0 = hh*2;
                    const int id = mt*2 + hh;
                    float mx = NEG_INF;
#pragma unroll
                    for (int nt = 0; nt < 8; nt++)
                        mx = fmaxf(mx, fmaxf(s[mt][nt][e0], s[mt][nt][e0+1]));
                    mx = fmaxf(mx, __shfl_xor_sync(0xffffffffu, mx, 1));
                    mx = fmaxf(mx, __shfl_xor_sync(0xffffffffu, mx, 2));
                    const float mnew = fmaxf(mrow[id], mx);
                    const float al = ex2f(mrow[id] - mnew);
                    mrow[id] = mnew;
                    float ls = 0.0f;
#pragma unroll
                    for (int nt = 0; nt < 8; nt++) {
                        float p0 = ex2f(s[mt][nt][e0]   - mnew);
                        float p1 = ex2f(s[mt][nt][e0+1] - mnew);
                        s[mt][nt][e0]   = p0;
                        s[mt][nt][e0+1] = p1;
                        ls += p0 + p1;
                    }
                    ls += __shfl_xor_sync(0xffffffffu, ls, 1);
                    ls += __shfl_xor_sync(0xffffffffu, ls, 2);
                    lrow[id] = lrow[id] * al + ls;
                    alpha[id] = al;
                }
            }
#pragma unroll
            for (int mt = 0; mt < 2; mt++)
#pragma unroll
                for (int nt = 0; nt < 8; nt++) {
                    o[mt][nt][0] *= alpha[mt*2];
                    o[mt][nt][1] *= alpha[mt*2];
                    o[mt][nt][2] *= alpha[mt*2+1];
                    o[mt][nt][3] *= alpha[mt*2+1];
                }

#pragma unroll
            for (int kk = 0; kk < 4; kk++) {
                uint32_t vh[4][4], vl[4][4];
#pragma unroll
                for (int nt2 = 0; nt2 < 4; nt2++) {
                    uint32_t off = ((nt2*16 + b_r) * ALD + kk*16 + b_c) * 2;
                    ldsm_x4(vh[nt2][0], vh[nt2][1], vh[nt2][2], vh[nt2][3], uVh + off);
                    ldsm_x4(vl[nt2][0], vl[nt2][1], vl[nt2][2], vl[nt2][3], uVl + off);
                }
#pragma unroll
                for (int mt = 0; mt < 2; mt++) {
                    uint32_t ph[4], pl[4];
                    split2(s[mt][2*kk][0],   s[mt][2*kk][1],   ph[0], pl[0]);
                    split2(s[mt][2*kk][2],   s[mt][2*kk][3],   ph[1], pl[1]);
                    split2(s[mt][2*kk+1][0], s[mt][2*kk+1][1], ph[2], pl[2]);
                    split2(s[mt][2*kk+1][2], s[mt][2*kk+1][3], ph[3], pl[3]);
#pragma unroll
                    for (int nt2 = 0; nt2 < 4; nt2++) {
                        float* d0 = o[mt][2*nt2];
                        float* d1 = o[mt][2*nt2+1];
                        mma_bf16(d0[0],d0[1],d0[2],d0[3],
                                 ph[0],ph[1],ph[2],ph[3],
                                 vh[nt2][0],vh[nt2][1]);
                        mma_bf16(d1[0],d1[1],d1[2],d1[3],
                                 ph[0],ph[1],ph[2],ph[3],
                                 vh[nt2][2],vh[nt2][3]);
                        mma_bf16(d0[0],d0[1],d0[2],d0[3],
                                 ph[0],ph[1],ph[2],ph[3],
                                 vl[nt2][0],vl[nt2][1]);
                        mma_bf16(d1[0],d1[1],d1[2],d1[3],
                                 ph[0],ph[1],ph[2],ph[3],
                                 vl[nt2][2],vl[nt2][3]);
                        mma_bf16(d0[0],d0[1],d0[2],d0[3],
                                 pl[0],pl[1],pl[2],pl[3],
                                 vh[nt2][0],vh[nt2][1]);
                        mma_bf16(d1[0],d1[1],d1[2],d1[3],
                                 pl[0],pl[1],pl[2],pl[3],
                                 vh[nt2][2],vh[nt2][3]);
                    }
                }
            }
        }
        __syncthreads();
    }

#pragma unroll
    for (int mt = 0; mt < 2; mt++) {
#pragma unroll
        for (int hh = 0; hh < 2; hh++) {
            const float inv = 1.0f / lrow[mt*2 + hh];
            const int row = qt*128 + wm*32 + mt*16 + lr + hh*8;
            float* yp = y + ((size_t)(b*TLEN + row))*CDIM + h*64;
#pragma unroll
            for (int nt = 0; nt < 8; nt++) {
                float2 v;
                v.x = o[mt][nt][hh*2]   * inv;
                v.y = o[mt][nt][hh*2+1] * inv;
                *reinterpret_cast<float2*>(yp + nt*8 + lc2) = v;
            }
        }
    }
}

// ---------------------------------------------------------------------------
// Launch
// ---------------------------------------------------------------------------
extern "C" void kernel_launch(void* const* d_in, const int* in_sizes, int n_in,
                              void* d_out, int out_size)
{
    (void)in_sizes; (void)n_in; (void)out_size;
    const float* x      = (const float*)d_in[0];
    const float* W_attn = (const float*)d_in[1];
    const float* b_attn = (const float*)d_in[2];
    const float* W_proj = (const float*)d_in[3];
    const float* b_proj = (const float*)d_in[4];
    float* out = (float*)d_out;

    float *qkv_ptr, *y_ptr;
    __nv_bfloat16 *ah, *al, *wah, *wal, *wph, *wpl;
    __nv_bfloat16 *qh2, *ql2, *kh2, *kl2, *vth, *vtl;
    cudaGetSymbolAddress((void**)&qkv_ptr, g_qkv);
    cudaGetSymbolAddress((void**)&y_ptr,   g_y);
    cudaGetSymbolAddress((void**)&ah,  g_ah);
    cudaGetSymbolAddress((void**)&al,  g_al);
    cudaGetSymbolAddress((void**)&wah, g_wah);
    cudaGetSymbolAddress((void**)&wal, g_wal);
    cudaGetSymbolAddress((void**)&wph, g_wph);
    cudaGetSymbolAddress((void**)&wpl, g_wpl);
    cudaGetSymbolAddress((void**)&qh2, g_qh2);
    cudaGetSymbolAddress((void**)&ql2, g_ql2);
    cudaGetSymbolAddress((void**)&kh2, g_kh2);
    cudaGetSymbolAddress((void**)&kl2, g_kl2);
    cudaGetSymbolAddress((void**)&vth, g_vth);
    cudaGetSymbolAddress((void**)&vtl, g_vtl);

    static bool attr_set = false;
    if (!attr_set) {
        cudaFuncSetAttribute(gemm_hmma_kernel,
                             cudaFuncAttributeMaxDynamicSharedMemorySize,
                             GEMM_SMEM_BYTES);
        cudaFuncSetAttribute(attn_mma_kernel,
                             cudaFuncAttributeMaxDynamicSharedMemorySize,
                             ATTN_SMEM_BYTES);
        attr_set = true;
    }

    const int M = MROWS;

    // Prep: split x; transpose+split weights
    {
        int n4 = M * CDIM / 4;
        split_kernel<<<(n4 + 255)/256, 256>>>(x, ah, al, n4);
        dim3 tb(32, 8);
        transpose_split_kernel<<<dim3(3*CDIM/32, CDIM/32), tb>>>(W_attn, wah, wal, CDIM, 3*CDIM);
        transpose_split_kernel<<<dim3(CDIM/32, CDIM/32), tb>>>(W_proj, wph, wpl, CDIM, CDIM);
    }

    // 1) QKV GEMM
    gemm_hmma_kernel<<<dim3(3*CDIM/128, M/128), 128, GEMM_SMEM_BYTES>>>(
        ah, al, wah, wal, b_attn, qkv_ptr, 3*CDIM, CDIM);

    // 2) attention prep
    {
        int n = BSZ*TLEN*2*HN*16;
        split_qk_kernel<<<(n + 255)/256, 256>>>(qkv_ptr, qh2, ql2, kh2, kl2);
        dim3 tb(32, 8);
        transpose_split_v_kernel<<<dim3(BSZ*HN, TLEN/32, 2), tb>>>(qkv_ptr, vth, vtl);
    }

    // 3) flash attention (HMMA)
    attn_mma_kernel<<<dim3(TLEN/128, BSZ*HN), 128, ATTN_SMEM_BYTES>>>(
        qh2, ql2, kh2, kl2, vth, vtl, y_ptr);

    // 4) split y, proj GEMM
    {
        int n4 = M * CDIM / 4;
        split_kernel<<<(n4 + 255)/256, 256>>>(y_ptr, ah, al, n4);
    }
    gemm_hmma_kernel<<<dim3(CDIM/128, M/128), 128, GEMM_SMEM_BYTES>>>(
        ah, al, wph, wpl, b_proj, out, CDIM, CDIM);
}